// round 10
// baseline (speedup 1.0000x reference)
#include <cuda_runtime.h>
#include <math.h>

#define NN 50000
#define EE 250000
#define GG 512
#define NB_SCAN 49
#define NPB 32
#define FUSE_GRID ((NN + NPB - 1) / NPB)  // 1563
#define FUSE_THREADS 512
#define OPAD 36

// ---------------- device scratch (allocation-free) ----------------
__device__ float g_out[NN * 32];
__device__ float g_q[EE * 32];
__device__ float g_agg[NN * 32];        // invariant: zero at launch entry
__device__ float g_probe[NN * 32];      // probe-only sink
__device__ float g_Wt[32 * 1024];
__device__ float g_WihT[32 * 96];
__device__ float g_WhhT[32 * 96];
__device__ int   g_hist[NN];            // invariant: zero at entry
__device__ int   g_rowstart[NN + 32];
__device__ int   g_cursor[NN];
__device__ int   g_blocksum[NB_SCAN];
__device__ int   g_blockoff[NB_SCAN];
__device__ int   g_order[EE];
__device__ int   g_srcs[EE];
__device__ int   g_dsts[EE];
__device__ float g_deg[NN];             // invariant: zero at entry
__device__ float g_pooled[GG * 32];     // invariant: zero at entry
__device__ float g_gcnt[GG];            // invariant: zero at entry

#define FULL 0xffffffffu

__device__ __forceinline__ void fma2(unsigned long long& d,
                                     unsigned long long a, unsigned long long b) {
    asm("fma.rn.f32x2 %0, %1, %2, %0;" : "+l"(d) : "l"(a), "l"(b));
}
__device__ __forceinline__ unsigned long long pack2(float lo, float hi) {
    unsigned long long r;
    asm("mov.b64 %0, {%1, %2};" : "=l"(r) : "f"(lo), "f"(hi));
    return r;
}
__device__ __forceinline__ float2 unpack2(unsigned long long v) {
    float2 f;
    asm("mov.b64 {%0, %1}, %2;" : "=f"(f.x), "=f"(f.y) : "l"(v));
    return f;
}

// ---------------- kernels ----------------

// 1024 threads, 32 nodes/block: 4x fewer weight-staging loads
__global__ void __launch_bounds__(1024) k_lin0(const float* __restrict__ x,
                                               const float* __restrict__ W0,
                                               const float* __restrict__ b0) {
    __shared__ float s_w[1024];
    __shared__ float s_b[32];
    int t = threadIdx.x;
    if (t < 1024) s_w[t] = W0[t];
    if (t < 32) s_b[t] = b0[t];
    __syncthreads();
    int w = t >> 5, lane = t & 31;
    int n = blockIdx.x * 32 + w;
    if (n >= NN) return;
    float xv = x[n * 32 + lane];
    float acc = s_b[lane];
#pragma unroll
    for (int i = 0; i < 32; i++)
        acc = fmaf(__shfl_sync(FULL, xv, i), s_w[i * 32 + lane], acc);
    g_out[n * 32 + lane] = fmaxf(acc, 0.f);
}

__global__ void k_prep(const float* __restrict__ We2, const float* __restrict__ Wih,
                       const float* __restrict__ Whh) {
    int i = blockIdx.x * blockDim.x + threadIdx.x;
    if (i < 32 * 1024) {
        int h = i >> 10, c = i & 1023, k = c >> 5, o = c & 31;
        g_Wt[i] = We2[k * 1024 + h * 32 + o];
    }
    if (i < 32 * 96) {
        int h = i / 96, j = i % 96;
        g_WihT[i] = Wih[j * 32 + h];
        g_WhhT[i] = Whh[j * 32 + h];
    }
}

__global__ void k_hist(const int* __restrict__ ei) {
    int e = blockIdx.x * blockDim.x + threadIdx.x;
    if (e >= EE) return;
    atomicAdd(&g_hist[ei[e]], 1);
    atomicAdd(&g_deg[ei[EE + e]], 1.f);
}

__global__ void k_scan_block() {
    __shared__ int s[1024];
    int t = threadIdx.x;
    int i = blockIdx.x * 1024 + t;
    int v = (i < NN) ? g_hist[i] : 0;
    s[t] = v;
    __syncthreads();
#pragma unroll
    for (int off = 1; off < 1024; off <<= 1) {
        int xv = (t >= off) ? s[t - off] : 0;
        __syncthreads();
        s[t] += xv;
        __syncthreads();
    }
    if (i < NN) g_rowstart[i] = s[t] - v;
    if (t == 1023) g_blocksum[blockIdx.x] = s[1023];
}

__global__ void k_scan_sums() {
    if (threadIdx.x == 0) {
        int acc = 0;
        for (int b = 0; b < NB_SCAN; b++) { g_blockoff[b] = acc; acc += g_blocksum[b]; }
    }
}

__global__ void k_scan_add() {
    int i = blockIdx.x * blockDim.x + threadIdx.x;
    if (i >= NN) return;
    int v = g_rowstart[i] + g_blockoff[i >> 10];
    g_rowstart[i] = v;
    g_cursor[i] = v;
    g_hist[i] = 0;
}

__global__ void k_order(const int* __restrict__ ei) {
    int e = blockIdx.x * blockDim.x + threadIdx.x;
    if (e >= EE) return;
    int pos = atomicAdd(&g_cursor[ei[e]], 1);
    g_order[pos] = e;
}

// 1024 threads, 32 edges/block
__global__ void __launch_bounds__(1024) k_permq(const float* __restrict__ ea,
                                                const int* __restrict__ ei,
                                                const float* __restrict__ We1,
                                                const float* __restrict__ be1) {
    __shared__ float s_w[512];
    __shared__ float s_b[32];
    int t = threadIdx.x;
    if (t < 512) s_w[t] = We1[t];
    if (t < 32) s_b[t] = be1[t];
    __syncthreads();
    int w = t >> 5, lane = t & 31;
    int i = blockIdx.x * 32 + w;
    if (i >= EE) return;
    int e = g_order[i];
    float eav = (lane < 16) ? __ldg(&ea[(size_t)e * 16 + lane]) : 0.f;
    float acc = s_b[lane];
#pragma unroll
    for (int k = 0; k < 16; k++)
        acc = fmaf(__shfl_sync(FULL, eav, k), s_w[k * 32 + lane], acc);
    g_q[(size_t)i * 32 + lane] = fmaxf(acc, 0.f);
    if (lane == 0) { g_srcs[i] = ei[e]; g_dsts[i] = ei[EE + e]; }
}

// ---- FUSED (R7 champion config): U (32 nodes) in SMEM via FFMA2, edge msg, scatter ----
__global__ void __launch_bounds__(FUSE_THREADS) k_fused(const float* __restrict__ be2,
                                                        int probe) {
    extern __shared__ float sm[];
    float* U_s  = sm;                           // [32][1024]
    float* o_sT = sm + 32 * 1024;               // [32][OPAD]
    float* bt_s = sm + 32 * 1024 + 32 * OPAD;   // [32][32]

    int t = threadIdx.x, lane = t & 31, w = t >> 5;
    int n0 = blockIdx.x * NPB;

    // load out tile transposed: o_sT[h][n], zero-fill OOB
#pragma unroll
    for (int r = 0; r < 2; r++) {
        int idx = t + r * 512;
        int n = idx >> 5, h = idx & 31;
        int gidx = n0 * 32 + idx;
        o_sT[h * OPAD + n] = (gidx < NN * 32) ? g_out[gidx] : 0.f;
    }
    __syncthreads();

    // bias term bt[n][o] (warp handles nodes w and w+16)
#pragma unroll
    for (int r = 0; r < 2; r++) {
        int n = w + r * 16;
        float acc = 0.f;
#pragma unroll
        for (int h = 0; h < 32; h++)
            acc = fmaf(o_sT[h * OPAD + n], __ldg(&be2[h * 32 + lane]), acc);
        bt_s[n * 32 + lane] = acc;
    }

    // U phase: thread t owns cols (2t,2t+1) for all 32 nodes, FFMA2 over node pairs
    {
        unsigned long long accA[16], accB[16];
#pragma unroll
        for (int p = 0; p < 16; p++) { accA[p] = 0ull; accB[p] = 0ull; }
        const float2* Wt2 = (const float2*)g_Wt;
#pragma unroll
        for (int h = 0; h < 32; h++) {
            float2 wv = __ldg(&Wt2[h * 512 + t]);
            unsigned long long wxx = pack2(wv.x, wv.x);
            unsigned long long wyy = pack2(wv.y, wv.y);
            const float* row = o_sT + h * OPAD;
#pragma unroll
            for (int q4 = 0; q4 < 8; q4++) {
                ulonglong2 ov = *(const ulonglong2*)(row + q4 * 4);
                fma2(accA[q4 * 2 + 0], ov.x, wxx);
                fma2(accA[q4 * 2 + 1], ov.y, wxx);
                fma2(accB[q4 * 2 + 0], ov.x, wyy);
                fma2(accB[q4 * 2 + 1], ov.y, wyy);
            }
        }
#pragma unroll
        for (int p = 0; p < 16; p++) {
            float2 a = unpack2(accA[p]);
            float2 b = unpack2(accB[p]);
            *(float2*)(U_s + (p * 2 + 0) * 1024 + 2 * t) = make_float2(a.x, b.x);
            *(float2*)(U_s + (p * 2 + 1) * 1024 + 2 * t) = make_float2(a.y, b.y);
        }
    }
    __syncthreads();

    // edge phase: 4 edges per warp iter
    int estart = g_rowstart[n0];
    int eend = (n0 + NPB >= NN) ? EE : g_rowstart[n0 + NPB];
    float* aggdst = probe ? g_probe : g_agg;
    int osub = (lane & 7) * 4;
    for (int base = estart + w * 4; base < eend; base += 16 * 4) {
        int e = base + (lane >> 3);
        bool valid = e < eend;
        int sl = 0, d = 0;
        float4 q4 = make_float4(0.f, 0.f, 0.f, 0.f);
        if (valid) {
            sl = g_srcs[e] - n0;
            d = g_dsts[e];
            q4 = *(const float4*)(g_q + (size_t)e * 32 + osub);
        }
        const float* Ub = U_s + sl * 1024 + osub;
        float4 bt4 = *(const float4*)(bt_s + sl * 32 + osub);
        unsigned long long m01 = pack2(bt4.x, bt4.y);
        unsigned long long m23 = pack2(bt4.z, bt4.w);
#pragma unroll
        for (int k = 0; k < 32; k++) {
            float comp = (k & 3) == 0 ? q4.x : (k & 3) == 1 ? q4.y
                       : (k & 3) == 2 ? q4.z : q4.w;
            float qk = __shfl_sync(FULL, comp, (lane & 24) + (k >> 2));
            unsigned long long qq = pack2(qk, qk);
            ulonglong2 uv = *(const ulonglong2*)(Ub + k * 32);
            fma2(m01, uv.x, qq);
            fma2(m23, uv.y, qq);
        }
        if (valid) {
            float2 a = unpack2(m01), b = unpack2(m23);
            atomicAdd((float4*)(aggdst + (size_t)d * 32 + osub),
                      make_float4(a.x, a.y, b.x, b.y));
        }
    }
}

// 1024 threads, warp handles 4 nodes -> 128 nodes/block (4x fewer staging loads)
__global__ void __launch_bounds__(1024) k_combine(
        const float* __restrict__ Wroot, const float* __restrict__ bconv,
        const float* __restrict__ bih, const float* __restrict__ bhh) {
    __shared__ float s_wr[1024];
    __shared__ float s_wi[3072];
    __shared__ float s_wh[3072];
    __shared__ float s_b[224];
    int t = threadIdx.x;
    if (t < 1024) s_wr[t] = Wroot[t];
    for (int i = t; i < 3072; i += 1024) { s_wi[i] = g_WihT[i]; s_wh[i] = g_WhhT[i]; }
    if (t < 32) s_b[t] = bconv[t];
    if (t < 96) s_b[32 + t] = bih[t];
    if (t < 96) s_b[128 + t] = bhh[t];
    __syncthreads();

    int w = t >> 5, lane = t & 31;
    int n0 = (blockIdx.x * 32 + w) * 4;
    if (n0 >= NN) return;

    float hv[4], m[4];
#pragma unroll
    for (int r = 0; r < 4; r++) {
        int n = n0 + r;
        float aggv = g_agg[n * 32 + lane];
        g_agg[n * 32 + lane] = 0.f;
        hv[r] = g_out[n * 32 + lane];
        m[r] = s_b[lane] + aggv / fmaxf(g_deg[n], 1.f);
    }
#pragma unroll
    for (int h = 0; h < 32; h++) {
        float wr = s_wr[h * 32 + lane];
#pragma unroll
        for (int r = 0; r < 4; r++)
            m[r] = fmaf(__shfl_sync(FULL, hv[r], h), wr, m[r]);
    }
#pragma unroll
    for (int r = 0; r < 4; r++) m[r] = fmaxf(m[r], 0.f);

    float gr[4], gz[4], gn[4], hr[4], hz[4], hn[4];
#pragma unroll
    for (int r = 0; r < 4; r++) {
        gr[r] = s_b[32 + lane]; gz[r] = s_b[64 + lane]; gn[r] = s_b[96 + lane];
        hr[r] = s_b[128 + lane]; hz[r] = s_b[160 + lane]; hn[r] = s_b[192 + lane];
    }
#pragma unroll
    for (int h = 0; h < 32; h++) {
        float wi0 = s_wi[h * 96 + lane];
        float wi1 = s_wi[h * 96 + 32 + lane];
        float wi2 = s_wi[h * 96 + 64 + lane];
        float wh0 = s_wh[h * 96 + lane];
        float wh1 = s_wh[h * 96 + 32 + lane];
        float wh2 = s_wh[h * 96 + 64 + lane];
#pragma unroll
        for (int r = 0; r < 4; r++) {
            float mh = __shfl_sync(FULL, m[r], h);
            float hh = __shfl_sync(FULL, hv[r], h);
            gr[r] = fmaf(mh, wi0, gr[r]);
            gz[r] = fmaf(mh, wi1, gz[r]);
            gn[r] = fmaf(mh, wi2, gn[r]);
            hr[r] = fmaf(hh, wh0, hr[r]);
            hz[r] = fmaf(hh, wh1, hz[r]);
            hn[r] = fmaf(hh, wh2, hn[r]);
        }
    }
#pragma unroll
    for (int r = 0; r < 4; r++) {
        float rr = 1.f / (1.f + __expf(-(gr[r] + hr[r])));
        float zz = 1.f / (1.f + __expf(-(gz[r] + hz[r])));
        float nn2 = tanhf(gn[r] + rr * hn[r]);
        g_out[(n0 + r) * 32 + lane] = (1.f - zz) * nn2 + zz * hv[r];
    }
}

__global__ void k_pool(const int* __restrict__ batch) {
    int gt = blockIdx.x * blockDim.x + threadIdx.x;
    int n = gt >> 5, lane = gt & 31;
    if (n >= NN) return;
    int b = __ldg(&batch[n]);
    atomicAdd(&g_pooled[b * 32 + lane], g_out[n * 32 + lane]);
    if (lane == 0) { atomicAdd(&g_gcnt[b], 1.f); g_deg[n] = 0.f; }
}

__global__ void k_head(const float* __restrict__ W1a, const float* __restrict__ b1a,
                       const float* __restrict__ W1b, const float* __restrict__ b1b,
                       const float* __restrict__ W2a, const float* __restrict__ b2a,
                       const float* __restrict__ W2b, const float* __restrict__ b2b,
                       float* __restrict__ out, int out_size) {
    int gt = blockIdx.x * blockDim.x + threadIdx.x;
    int g = gt >> 5, lane = gt & 31;
    if (g >= GG) return;
    float c = fmaxf(g_gcnt[g], 1.f);
    float pm = g_pooled[g * 32 + lane] / c;
    g_pooled[g * 32 + lane] = 0.f;
    if (lane == 0) g_gcnt[g] = 0.f;
    float t1 = __ldg(&b1a[lane]);
    float t2 = __ldg(&b2a[lane]);
#pragma unroll
    for (int h = 0; h < 32; h++) {
        float ph = __shfl_sync(FULL, pm, h);
        t1 = fmaf(ph, __ldg(&W1a[h * 32 + lane]), t1);
        t2 = fmaf(ph, __ldg(&W2a[h * 32 + lane]), t2);
    }
    t1 = fmaxf(t1, 0.f);
    t2 = fmaxf(t2, 0.f);
    float lv = t1 * __ldg(&W1b[lane]);
    float d0 = t2 * __ldg(&W2b[lane * 2]);
    float d1 = t2 * __ldg(&W2b[lane * 2 + 1]);
#pragma unroll
    for (int off = 16; off; off >>= 1) {
        lv += __shfl_xor_sync(FULL, lv, off);
        d0 += __shfl_xor_sync(FULL, d0, off);
        d1 += __shfl_xor_sync(FULL, d1, off);
    }
    if (lane == 0) {
        float lab = lv + __ldg(&b1b[0]);
        float a0 = d0 + __ldg(&b2b[0]);
        float a1 = d1 + __ldg(&b2b[1]);
        float mx = fmaxf(a0, a1);
        float ls = mx + logf(expf(a0 - mx) + expf(a1 - mx));
        out[g] = lab;
        if (out_size >= GG * 3) {
            out[GG + g * 2]     = a0 - ls;
            out[GG + g * 2 + 1] = a1 - ls;
        }
    }
}

// ---------------- launch ----------------
extern "C" void kernel_launch(void* const* d_in, const int* in_sizes, int n_in,
                              void* d_out, int out_size) {
    const float* x     = (const float*)d_in[0];
    const float* ea    = (const float*)d_in[1];
    const int*   ei    = (const int*)d_in[2];
    const int*   batch = (const int*)d_in[3];
    const float* W0    = (const float*)d_in[5];
    const float* b0    = (const float*)d_in[6];
    const float* We1   = (const float*)d_in[7];
    const float* be1   = (const float*)d_in[8];
    const float* We2   = (const float*)d_in[9];
    const float* be2   = (const float*)d_in[10];
    const float* Wroot = (const float*)d_in[11];
    const float* bconv = (const float*)d_in[12];
    const float* Wih   = (const float*)d_in[13];
    const float* bih   = (const float*)d_in[14];
    const float* Whh   = (const float*)d_in[15];
    const float* bhh   = (const float*)d_in[16];
    const float* W1a   = (const float*)d_in[17];
    const float* b1a   = (const float*)d_in[18];
    const float* W1b   = (const float*)d_in[19];
    const float* b1b   = (const float*)d_in[20];
    const float* W2a   = (const float*)d_in[21];
    const float* b2a   = (const float*)d_in[22];
    const float* W2b   = (const float*)d_in[23];
    const float* b2b   = (const float*)d_in[24];
    float* out = (float*)d_out;

    const int TPB = 256;
    const int FUSE_SMEM = (32 * 1024 + 32 * OPAD + 32 * 32) * 4;  // 139776 B
    cudaFuncSetAttribute(k_fused, cudaFuncAttributeMaxDynamicSharedMemorySize, FUSE_SMEM);

    k_lin0<<<(NN + 31) / 32, 1024>>>(x, W0, b0);                      // 1
    k_prep<<<(32 * 1024 + TPB - 1) / TPB, TPB>>>(We2, Wih, Whh);      // 2
    k_hist<<<(EE + TPB - 1) / TPB, TPB>>>(ei);                        // 3
    k_fused<<<148, FUSE_THREADS, FUSE_SMEM>>>(be2, 1);                // 4: ncu probe
    k_scan_block<<<NB_SCAN, 1024>>>();                                // 5
    k_scan_sums<<<1, 32>>>();                                         // 6
    k_scan_add<<<(NN + TPB - 1) / TPB, TPB>>>();                      // 7
    k_order<<<(EE + TPB - 1) / TPB, TPB>>>(ei);                       // 8
    k_permq<<<(EE + 31) / 32, 1024>>>(ea, ei, We1, be1);              // 9

    for (int it = 0; it < 3; it++) {
        k_fused<<<FUSE_GRID, FUSE_THREADS, FUSE_SMEM>>>(be2, 0);
        k_combine<<<(NN / 4 + 31) / 32, 1024>>>(Wroot, bconv, bih, bhh);
    }

    k_pool<<<(NN * 32 + TPB - 1) / TPB, TPB>>>(batch);
    k_head<<<(GG * 32 + TPB - 1) / TPB, TPB>>>(W1a, b1a, W1b, b1b,
                                               W2a, b2a, W2b, b2b, out, out_size);
}

// round 11
// speedup vs baseline: 1.0730x; 1.0730x over previous
#include <cuda_runtime.h>
#include <math.h>

#define NN 50000
#define EE 250000
#define GG 512
#define NB_SCAN 49
#define NPB 32
#define FUSE_GRID ((NN + NPB - 1) / NPB)  // 1563
#define FUSE_THREADS 512
#define OPAD 36

// ---------------- device scratch (allocation-free) ----------------
__device__ float g_out[NN * 32];
__device__ float g_q[EE * 32];
__device__ float g_agg[NN * 32];        // invariant: zero at launch entry
__device__ float g_probe[NN * 32];      // probe-only sink
__device__ float g_Wt[32 * 1024];
__device__ float g_WihT[32 * 96];
__device__ float g_WhhT[32 * 96];
__device__ int   g_hist[NN];            // invariant: zero at entry
__device__ int   g_rowstart[NN + 32];
__device__ int   g_cursor[NN];
__device__ int   g_blocksum[NB_SCAN];
__device__ int   g_blockoff[NB_SCAN];
__device__ int   g_order[EE];
__device__ int   g_srcs[EE];
__device__ int   g_dsts[EE];
__device__ float g_deg[NN];             // invariant: zero at entry
__device__ float g_pooled[GG * 32];     // invariant: zero at entry
__device__ float g_gcnt[GG];            // invariant: zero at entry

#define FULL 0xffffffffu

__device__ __forceinline__ void fma2(unsigned long long& d,
                                     unsigned long long a, unsigned long long b) {
    asm("fma.rn.f32x2 %0, %1, %2, %0;" : "+l"(d) : "l"(a), "l"(b));
}
__device__ __forceinline__ unsigned long long pack2(float lo, float hi) {
    unsigned long long r;
    asm("mov.b64 %0, {%1, %2};" : "=l"(r) : "f"(lo), "f"(hi));
    return r;
}
__device__ __forceinline__ float2 unpack2(unsigned long long v) {
    float2 f;
    asm("mov.b64 {%0, %1}, %2;" : "=f"(f.x), "=f"(f.y) : "l"(v));
    return f;
}

// ---------------- kernels ----------------

// R7 version: 256 threads, 8 nodes/block
__global__ void k_lin0(const float* __restrict__ x, const float* __restrict__ W0,
                       const float* __restrict__ b0) {
    __shared__ float s_w[1024];
    __shared__ float s_b[32];
    int t = threadIdx.x;
    for (int i = t; i < 1024; i += 256) s_w[i] = W0[i];
    if (t < 32) s_b[t] = b0[t];
    __syncthreads();
    int w = t >> 5, lane = t & 31;
    int n = blockIdx.x * 8 + w;
    if (n >= NN) return;
    float xv = x[n * 32 + lane];
    float acc = s_b[lane];
#pragma unroll
    for (int i = 0; i < 32; i++)
        acc = fmaf(__shfl_sync(FULL, xv, i), s_w[i * 32 + lane], acc);
    g_out[n * 32 + lane] = fmaxf(acc, 0.f);
}

__global__ void k_prep(const float* __restrict__ We2, const float* __restrict__ Wih,
                       const float* __restrict__ Whh) {
    int i = blockIdx.x * blockDim.x + threadIdx.x;
    if (i < 32 * 1024) {
        int h = i >> 10, c = i & 1023, k = c >> 5, o = c & 31;
        g_Wt[i] = We2[k * 1024 + h * 32 + o];
    }
    if (i < 32 * 96) {
        int h = i / 96, j = i % 96;
        g_WihT[i] = Wih[j * 32 + h];
        g_WhhT[i] = Whh[j * 32 + h];
    }
}

__global__ void k_hist(const int* __restrict__ ei) {
    int e = blockIdx.x * blockDim.x + threadIdx.x;
    if (e >= EE) return;
    atomicAdd(&g_hist[ei[e]], 1);
    atomicAdd(&g_deg[ei[EE + e]], 1.f);
}

__global__ void k_scan_block() {
    __shared__ int s[1024];
    int t = threadIdx.x;
    int i = blockIdx.x * 1024 + t;
    int v = (i < NN) ? g_hist[i] : 0;
    s[t] = v;
    __syncthreads();
#pragma unroll
    for (int off = 1; off < 1024; off <<= 1) {
        int xv = (t >= off) ? s[t - off] : 0;
        __syncthreads();
        s[t] += xv;
        __syncthreads();
    }
    if (i < NN) g_rowstart[i] = s[t] - v;
    if (t == 1023) g_blocksum[blockIdx.x] = s[1023];
}

__global__ void k_scan_sums() {
    if (threadIdx.x == 0) {
        int acc = 0;
        for (int b = 0; b < NB_SCAN; b++) { g_blockoff[b] = acc; acc += g_blocksum[b]; }
    }
}

__global__ void k_scan_add() {
    int i = blockIdx.x * blockDim.x + threadIdx.x;
    if (i >= NN) return;
    int v = g_rowstart[i] + g_blockoff[i >> 10];
    g_rowstart[i] = v;
    g_cursor[i] = v;
    g_hist[i] = 0;
}

__global__ void k_order(const int* __restrict__ ei) {
    int e = blockIdx.x * blockDim.x + threadIdx.x;
    if (e >= EE) return;
    int pos = atomicAdd(&g_cursor[ei[e]], 1);
    g_order[pos] = e;
}

// R7 version: 256 threads, 8 edges/block
__global__ void k_permq(const float* __restrict__ ea, const int* __restrict__ ei,
                        const float* __restrict__ We1, const float* __restrict__ be1) {
    __shared__ float s_w[512];
    __shared__ float s_b[32];
    int t = threadIdx.x;
    for (int i = t; i < 512; i += 256) s_w[i] = We1[i];
    if (t < 32) s_b[t] = be1[t];
    __syncthreads();
    int w = t >> 5, lane = t & 31;
    int i = blockIdx.x * 8 + w;
    if (i >= EE) return;
    int e = g_order[i];
    float eav = (lane < 16) ? __ldg(&ea[(size_t)e * 16 + lane]) : 0.f;
    float acc = s_b[lane];
#pragma unroll
    for (int k = 0; k < 16; k++)
        acc = fmaf(__shfl_sync(FULL, eav, k), s_w[k * 32 + lane], acc);
    g_q[(size_t)i * 32 + lane] = fmaxf(acc, 0.f);
    if (lane == 0) { g_srcs[i] = ei[e]; g_dsts[i] = ei[EE + e]; }
}

// ---- FUSED: Wt bulk-staged into smem (aliases U_s), U via FFMA2, edge msg, scatter ----
__global__ void __launch_bounds__(FUSE_THREADS) k_fused(const float* __restrict__ be2,
                                                        int probe) {
    extern __shared__ float sm[];
    float* UW_s = sm;                           // [32][1024]: Wt during U compute, U after
    float* o_sT = sm + 32 * 1024;               // [32][OPAD]
    float* bt_s = sm + 32 * 1024 + 32 * OPAD;   // [32][32]

    int t = threadIdx.x, lane = t & 31, w = t >> 5;
    int n0 = blockIdx.x * NPB;

    // 1. bulk-stage Wt (128 KB) into smem, 16-deep MLP, coalesced
    {
        const float4* src = (const float4*)g_Wt;
        float4* dst = (float4*)UW_s;
#pragma unroll
        for (int i = 0; i < 16; i++)
            dst[t + i * 512] = __ldg(&src[t + i * 512]);
    }

    // 2. load out tile transposed: o_sT[h][n], zero-fill OOB
#pragma unroll
    for (int r = 0; r < 2; r++) {
        int idx = t + r * 512;
        int n = idx >> 5, h = idx & 31;
        int gidx = n0 * 32 + idx;
        o_sT[h * OPAD + n] = (gidx < NN * 32) ? g_out[gidx] : 0.f;
    }
    __syncthreads();

    // 3. bias term bt[n][o] (warp handles nodes w and w+16)
#pragma unroll
    for (int r = 0; r < 2; r++) {
        int n = w + r * 16;
        float acc = 0.f;
#pragma unroll
        for (int h = 0; h < 32; h++)
            acc = fmaf(o_sT[h * OPAD + n], __ldg(&be2[h * 32 + lane]), acc);
        bt_s[n * 32 + lane] = acc;
    }

    // 4. U phase: thread t owns cols (2t,2t+1) for all 32 nodes; Wt read from SMEM
    unsigned long long accA[16], accB[16];
    {
#pragma unroll
        for (int p = 0; p < 16; p++) { accA[p] = 0ull; accB[p] = 0ull; }
#pragma unroll
        for (int h = 0; h < 32; h++) {
            float2 wv = *(const float2*)(UW_s + h * 1024 + 2 * t);   // LDS.64
            unsigned long long wxx = pack2(wv.x, wv.x);
            unsigned long long wyy = pack2(wv.y, wv.y);
            const float* row = o_sT + h * OPAD;
#pragma unroll
            for (int q4 = 0; q4 < 8; q4++) {
                ulonglong2 ov = *(const ulonglong2*)(row + q4 * 4);
                fma2(accA[q4 * 2 + 0], ov.x, wxx);
                fma2(accA[q4 * 2 + 1], ov.y, wxx);
                fma2(accB[q4 * 2 + 0], ov.x, wyy);
                fma2(accB[q4 * 2 + 1], ov.y, wyy);
            }
        }
    }
    __syncthreads();   // all Wt reads complete before overwriting with U

    // 5. store U over the Wt staging area
#pragma unroll
    for (int p = 0; p < 16; p++) {
        float2 a = unpack2(accA[p]);
        float2 b = unpack2(accB[p]);
        *(float2*)(UW_s + (p * 2 + 0) * 1024 + 2 * t) = make_float2(a.x, b.x);
        *(float2*)(UW_s + (p * 2 + 1) * 1024 + 2 * t) = make_float2(a.y, b.y);
    }
    __syncthreads();

    // 6. edge phase: 4 edges per warp iter
    int estart = g_rowstart[n0];
    int eend = (n0 + NPB >= NN) ? EE : g_rowstart[n0 + NPB];
    float* aggdst = probe ? g_probe : g_agg;
    int osub = (lane & 7) * 4;
    for (int base = estart + w * 4; base < eend; base += 16 * 4) {
        int e = base + (lane >> 3);
        bool valid = e < eend;
        int sl = 0, d = 0;
        float4 q4 = make_float4(0.f, 0.f, 0.f, 0.f);
        if (valid) {
            sl = g_srcs[e] - n0;
            d = g_dsts[e];
            q4 = *(const float4*)(g_q + (size_t)e * 32 + osub);
        }
        const float* Ub = UW_s + sl * 1024 + osub;
        float4 bt4 = *(const float4*)(bt_s + sl * 32 + osub);
        unsigned long long m01 = pack2(bt4.x, bt4.y);
        unsigned long long m23 = pack2(bt4.z, bt4.w);
#pragma unroll
        for (int k = 0; k < 32; k++) {
            float comp = (k & 3) == 0 ? q4.x : (k & 3) == 1 ? q4.y
                       : (k & 3) == 2 ? q4.z : q4.w;
            float qk = __shfl_sync(FULL, comp, (lane & 24) + (k >> 2));
            unsigned long long qq = pack2(qk, qk);
            ulonglong2 uv = *(const ulonglong2*)(Ub + k * 32);
            fma2(m01, uv.x, qq);
            fma2(m23, uv.y, qq);
        }
        if (valid) {
            float2 a = unpack2(m01), b = unpack2(m23);
            atomicAdd((float4*)(aggdst + (size_t)d * 32 + osub),
                      make_float4(a.x, a.y, b.x, b.y));
        }
    }
}

// R7 version: 256 threads, warp handles 4 nodes; re-zeroes agg
__global__ void __launch_bounds__(256) k_combine(
        const float* __restrict__ Wroot, const float* __restrict__ bconv,
        const float* __restrict__ bih, const float* __restrict__ bhh) {
    __shared__ float s_wr[1024];
    __shared__ float s_wi[3072];
    __shared__ float s_wh[3072];
    __shared__ float s_b[224];
    int t = threadIdx.x;
    for (int i = t; i < 1024; i += 256) s_wr[i] = Wroot[i];
    for (int i = t; i < 3072; i += 256) { s_wi[i] = g_WihT[i]; s_wh[i] = g_WhhT[i]; }
    if (t < 32) s_b[t] = bconv[t];
    if (t < 96) s_b[32 + t] = bih[t];
    if (t < 96) s_b[128 + t] = bhh[t];
    __syncthreads();

    int w = t >> 5, lane = t & 31;
    int n0 = (blockIdx.x * 8 + w) * 4;
    if (n0 >= NN) return;

    float hv[4], m[4];
#pragma unroll
    for (int r = 0; r < 4; r++) {
        int n = n0 + r;
        float aggv = g_agg[n * 32 + lane];
        g_agg[n * 32 + lane] = 0.f;
        hv[r] = g_out[n * 32 + lane];
        m[r] = s_b[lane] + aggv / fmaxf(g_deg[n], 1.f);
    }
#pragma unroll
    for (int h = 0; h < 32; h++) {
        float wr = s_wr[h * 32 + lane];
#pragma unroll
        for (int r = 0; r < 4; r++)
            m[r] = fmaf(__shfl_sync(FULL, hv[r], h), wr, m[r]);
    }
#pragma unroll
    for (int r = 0; r < 4; r++) m[r] = fmaxf(m[r], 0.f);

    float gr[4], gz[4], gn[4], hr[4], hz[4], hn[4];
#pragma unroll
    for (int r = 0; r < 4; r++) {
        gr[r] = s_b[32 + lane]; gz[r] = s_b[64 + lane]; gn[r] = s_b[96 + lane];
        hr[r] = s_b[128 + lane]; hz[r] = s_b[160 + lane]; hn[r] = s_b[192 + lane];
    }
#pragma unroll
    for (int h = 0; h < 32; h++) {
        float wi0 = s_wi[h * 96 + lane];
        float wi1 = s_wi[h * 96 + 32 + lane];
        float wi2 = s_wi[h * 96 + 64 + lane];
        float wh0 = s_wh[h * 96 + lane];
        float wh1 = s_wh[h * 96 + 32 + lane];
        float wh2 = s_wh[h * 96 + 64 + lane];
#pragma unroll
        for (int r = 0; r < 4; r++) {
            float mh = __shfl_sync(FULL, m[r], h);
            float hh = __shfl_sync(FULL, hv[r], h);
            gr[r] = fmaf(mh, wi0, gr[r]);
            gz[r] = fmaf(mh, wi1, gz[r]);
            gn[r] = fmaf(mh, wi2, gn[r]);
            hr[r] = fmaf(hh, wh0, hr[r]);
            hz[r] = fmaf(hh, wh1, hz[r]);
            hn[r] = fmaf(hh, wh2, hn[r]);
        }
    }
#pragma unroll
    for (int r = 0; r < 4; r++) {
        float rr = 1.f / (1.f + __expf(-(gr[r] + hr[r])));
        float zz = 1.f / (1.f + __expf(-(gz[r] + hz[r])));
        float nn2 = tanhf(gn[r] + rr * hn[r]);
        g_out[(n0 + r) * 32 + lane] = (1.f - zz) * nn2 + zz * hv[r];
    }
}

__global__ void k_pool(const int* __restrict__ batch) {
    int gt = blockIdx.x * blockDim.x + threadIdx.x;
    int n = gt >> 5, lane = gt & 31;
    if (n >= NN) return;
    int b = __ldg(&batch[n]);
    atomicAdd(&g_pooled[b * 32 + lane], g_out[n * 32 + lane]);
    if (lane == 0) { atomicAdd(&g_gcnt[b], 1.f); g_deg[n] = 0.f; }
}

__global__ void k_head(const float* __restrict__ W1a, const float* __restrict__ b1a,
                       const float* __restrict__ W1b, const float* __restrict__ b1b,
                       const float* __restrict__ W2a, const float* __restrict__ b2a,
                       const float* __restrict__ W2b, const float* __restrict__ b2b,
                       float* __restrict__ out, int out_size) {
    int gt = blockIdx.x * blockDim.x + threadIdx.x;
    int g = gt >> 5, lane = gt & 31;
    if (g >= GG) return;
    float c = fmaxf(g_gcnt[g], 1.f);
    float pm = g_pooled[g * 32 + lane] / c;
    g_pooled[g * 32 + lane] = 0.f;
    if (lane == 0) g_gcnt[g] = 0.f;
    float t1 = __ldg(&b1a[lane]);
    float t2 = __ldg(&b2a[lane]);
#pragma unroll
    for (int h = 0; h < 32; h++) {
        float ph = __shfl_sync(FULL, pm, h);
        t1 = fmaf(ph, __ldg(&W1a[h * 32 + lane]), t1);
        t2 = fmaf(ph, __ldg(&W2a[h * 32 + lane]), t2);
    }
    t1 = fmaxf(t1, 0.f);
    t2 = fmaxf(t2, 0.f);
    float lv = t1 * __ldg(&W1b[lane]);
    float d0 = t2 * __ldg(&W2b[lane * 2]);
    float d1 = t2 * __ldg(&W2b[lane * 2 + 1]);
#pragma unroll
    for (int off = 16; off; off >>= 1) {
        lv += __shfl_xor_sync(FULL, lv, off);
        d0 += __shfl_xor_sync(FULL, d0, off);
        d1 += __shfl_xor_sync(FULL, d1, off);
    }
    if (lane == 0) {
        float lab = lv + __ldg(&b1b[0]);
        float a0 = d0 + __ldg(&b2b[0]);
        float a1 = d1 + __ldg(&b2b[1]);
        float mx = fmaxf(a0, a1);
        float ls = mx + logf(expf(a0 - mx) + expf(a1 - mx));
        out[g] = lab;
        if (out_size >= GG * 3) {
            out[GG + g * 2]     = a0 - ls;
            out[GG + g * 2 + 1] = a1 - ls;
        }
    }
}

// ---------------- launch ----------------
extern "C" void kernel_launch(void* const* d_in, const int* in_sizes, int n_in,
                              void* d_out, int out_size) {
    const float* x     = (const float*)d_in[0];
    const float* ea    = (const float*)d_in[1];
    const int*   ei    = (const int*)d_in[2];
    const int*   batch = (const int*)d_in[3];
    const float* W0    = (const float*)d_in[5];
    const float* b0    = (const float*)d_in[6];
    const float* We1   = (const float*)d_in[7];
    const float* be1   = (const float*)d_in[8];
    const float* We2   = (const float*)d_in[9];
    const float* be2   = (const float*)d_in[10];
    const float* Wroot = (const float*)d_in[11];
    const float* bconv = (const float*)d_in[12];
    const float* Wih   = (const float*)d_in[13];
    const float* bih   = (const float*)d_in[14];
    const float* Whh   = (const float*)d_in[15];
    const float* bhh   = (const float*)d_in[16];
    const float* W1a   = (const float*)d_in[17];
    const float* b1a   = (const float*)d_in[18];
    const float* W1b   = (const float*)d_in[19];
    const float* b1b   = (const float*)d_in[20];
    const float* W2a   = (const float*)d_in[21];
    const float* b2a   = (const float*)d_in[22];
    const float* W2b   = (const float*)d_in[23];
    const float* b2b   = (const float*)d_in[24];
    float* out = (float*)d_out;

    const int TPB = 256;
    const int FUSE_SMEM = (32 * 1024 + 32 * OPAD + 32 * 32) * 4;  // 139776 B
    cudaFuncSetAttribute(k_fused, cudaFuncAttributeMaxDynamicSharedMemorySize, FUSE_SMEM);

    k_lin0<<<(NN + 7) / 8, 256>>>(x, W0, b0);                         // 1
    k_prep<<<(32 * 1024 + TPB - 1) / TPB, TPB>>>(We2, Wih, Whh);      // 2
    k_hist<<<(EE + TPB - 1) / TPB, TPB>>>(ei);                        // 3
    k_fused<<<148, FUSE_THREADS, FUSE_SMEM>>>(be2, 1);                // 4: ncu probe
    k_scan_block<<<NB_SCAN, 1024>>>();                                // 5
    k_scan_sums<<<1, 32>>>();                                         // 6
    k_scan_add<<<(NN + TPB - 1) / TPB, TPB>>>();                      // 7
    k_order<<<(EE + TPB - 1) / TPB, TPB>>>(ei);                       // 8
    k_permq<<<(EE + 7) / 8, 256>>>(ea, ei, We1, be1);                 // 9

    for (int it = 0; it < 3; it++) {
        k_fused<<<FUSE_GRID, FUSE_THREADS, FUSE_SMEM>>>(be2, 0);
        k_combine<<<(NN / 4 + 7) / 8, 256>>>(Wroot, bconv, bih, bhh);
    }

    k_pool<<<(NN * 32 + TPB - 1) / TPB, TPB>>>(batch);
    k_head<<<(GG * 32 + TPB - 1) / TPB, TPB>>>(W1a, b1a, W1b, b1b,
                                               W2a, b2a, W2b, b2b, out, out_size);
}

// round 12
// speedup vs baseline: 1.1719x; 1.0922x over previous
#include <cuda_runtime.h>
#include <math.h>

#define NN 50000
#define EE 250000
#define GG 512
#define NB_SCAN 49
#define NPB 16
#define FUSE_GRID (NN / NPB)            // 3125 exact
#define FUSE_THREADS 512
#define OPAD 20

// ---------------- device scratch (allocation-free) ----------------
__device__ float g_out[NN * 32];
__device__ float g_q[EE * 32];
__device__ float g_agg[NN * 32];        // invariant: zero at launch entry
__device__ float g_probe[NN * 32];      // probe-only sink
__device__ float g_Wt[32 * 1024];
__device__ float g_WihT[32 * 96];
__device__ float g_WhhT[32 * 96];
__device__ int   g_hist[NN];            // invariant: zero at entry
__device__ int   g_rowstart[NN + 32];
__device__ int   g_cursor[NN];
__device__ int   g_blocksum[NB_SCAN];
__device__ int   g_blockoff[NB_SCAN];
__device__ int   g_order[EE];
__device__ int   g_srcs[EE];
__device__ int   g_dsts[EE];
__device__ float g_deg[NN];             // invariant: zero at entry
__device__ float g_pooled[GG * 32];     // invariant: zero at entry
__device__ float g_gcnt[GG];            // invariant: zero at entry

#define FULL 0xffffffffu

__device__ __forceinline__ void fma2(unsigned long long& d,
                                     unsigned long long a, unsigned long long b) {
    asm("fma.rn.f32x2 %0, %1, %2, %0;" : "+l"(d) : "l"(a), "l"(b));
}
__device__ __forceinline__ unsigned long long pack2(float lo, float hi) {
    unsigned long long r;
    asm("mov.b64 %0, {%1, %2};" : "=l"(r) : "f"(lo), "f"(hi));
    return r;
}
__device__ __forceinline__ float2 unpack2(unsigned long long v) {
    float2 f;
    asm("mov.b64 {%0, %1}, %2;" : "=f"(f.x), "=f"(f.y) : "l"(v));
    return f;
}

// ---------------- kernels ----------------

// R7 version: 256 threads, 8 nodes/block
__global__ void k_lin0(const float* __restrict__ x, const float* __restrict__ W0,
                       const float* __restrict__ b0) {
    __shared__ float s_w[1024];
    __shared__ float s_b[32];
    int t = threadIdx.x;
    for (int i = t; i < 1024; i += 256) s_w[i] = W0[i];
    if (t < 32) s_b[t] = b0[t];
    __syncthreads();
    int w = t >> 5, lane = t & 31;
    int n = blockIdx.x * 8 + w;
    if (n >= NN) return;
    float xv = x[n * 32 + lane];
    float acc = s_b[lane];
#pragma unroll
    for (int i = 0; i < 32; i++)
        acc = fmaf(__shfl_sync(FULL, xv, i), s_w[i * 32 + lane], acc);
    g_out[n * 32 + lane] = fmaxf(acc, 0.f);
}

__global__ void k_prep(const float* __restrict__ We2, const float* __restrict__ Wih,
                       const float* __restrict__ Whh) {
    int i = blockIdx.x * blockDim.x + threadIdx.x;
    if (i < 32 * 1024) {
        int h = i >> 10, c = i & 1023, k = c >> 5, o = c & 31;
        g_Wt[i] = We2[k * 1024 + h * 32 + o];
    }
    if (i < 32 * 96) {
        int h = i / 96, j = i % 96;
        g_WihT[i] = Wih[j * 32 + h];
        g_WhhT[i] = Whh[j * 32 + h];
    }
}

__global__ void k_hist(const int* __restrict__ ei) {
    int e = blockIdx.x * blockDim.x + threadIdx.x;
    if (e >= EE) return;
    atomicAdd(&g_hist[ei[e]], 1);
    atomicAdd(&g_deg[ei[EE + e]], 1.f);
}

__global__ void k_scan_block() {
    __shared__ int s[1024];
    int t = threadIdx.x;
    int i = blockIdx.x * 1024 + t;
    int v = (i < NN) ? g_hist[i] : 0;
    s[t] = v;
    __syncthreads();
#pragma unroll
    for (int off = 1; off < 1024; off <<= 1) {
        int xv = (t >= off) ? s[t - off] : 0;
        __syncthreads();
        s[t] += xv;
        __syncthreads();
    }
    if (i < NN) g_rowstart[i] = s[t] - v;
    if (t == 1023) g_blocksum[blockIdx.x] = s[1023];
}

__global__ void k_scan_sums() {
    if (threadIdx.x == 0) {
        int acc = 0;
        for (int b = 0; b < NB_SCAN; b++) { g_blockoff[b] = acc; acc += g_blocksum[b]; }
    }
}

__global__ void k_scan_add() {
    int i = blockIdx.x * blockDim.x + threadIdx.x;
    if (i >= NN) return;
    int v = g_rowstart[i] + g_blockoff[i >> 10];
    g_rowstart[i] = v;
    g_cursor[i] = v;
    g_hist[i] = 0;
}

__global__ void k_order(const int* __restrict__ ei) {
    int e = blockIdx.x * blockDim.x + threadIdx.x;
    if (e >= EE) return;
    int pos = atomicAdd(&g_cursor[ei[e]], 1);
    g_order[pos] = e;
}

// R7 version: 256 threads, 8 edges/block
__global__ void k_permq(const float* __restrict__ ea, const int* __restrict__ ei,
                        const float* __restrict__ We1, const float* __restrict__ be1) {
    __shared__ float s_w[512];
    __shared__ float s_b[32];
    int t = threadIdx.x;
    for (int i = t; i < 512; i += 256) s_w[i] = We1[i];
    if (t < 32) s_b[t] = be1[t];
    __syncthreads();
    int w = t >> 5, lane = t & 31;
    int i = blockIdx.x * 8 + w;
    if (i >= EE) return;
    int e = g_order[i];
    float eav = (lane < 16) ? __ldg(&ea[(size_t)e * 16 + lane]) : 0.f;
    float acc = s_b[lane];
#pragma unroll
    for (int k = 0; k < 16; k++)
        acc = fmaf(__shfl_sync(FULL, eav, k), s_w[k * 32 + lane], acc);
    g_q[(size_t)i * 32 + lane] = fmaxf(acc, 0.f);
    if (lane == 0) { g_srcs[i] = ei[e]; g_dsts[i] = ei[EE + e]; }
}

// ---- FUSED: NPB=16, 2 blocks/SM (occupancy play); R7 instruction mix ----
__global__ void __launch_bounds__(FUSE_THREADS, 2) k_fused(const float* __restrict__ be2,
                                                           int probe) {
    extern __shared__ float sm[];
    float* U_s  = sm;                               // [16][1024]
    float* o_sT = sm + 16 * 1024;                   // [32][OPAD]
    float* bt_s = sm + 16 * 1024 + 32 * OPAD;       // [16][32]

    int t = threadIdx.x, lane = t & 31, w = t >> 5;
    int n0 = blockIdx.x * NPB;

    // load out tile transposed: o_sT[h][n] (512 elems, 1 per thread; NN%16==0 so no OOB)
    {
        int n = t >> 5, h = t & 31;
        o_sT[h * OPAD + n] = g_out[n0 * 32 + t];
    }
    __syncthreads();

    // bias term bt[n][o]: warp w -> node w (16 warps, 16 nodes)
    {
        float acc = 0.f;
#pragma unroll
        for (int h = 0; h < 32; h++)
            acc = fmaf(o_sT[h * OPAD + w], __ldg(&be2[h * 32 + lane]), acc);
        bt_s[w * 32 + lane] = acc;
    }

    // U phase: thread t owns cols (2t,2t+1) for 16 nodes (8 pairs, FFMA2)
    {
        unsigned long long accA[8], accB[8];
#pragma unroll
        for (int p = 0; p < 8; p++) { accA[p] = 0ull; accB[p] = 0ull; }
        const float2* Wt2 = (const float2*)g_Wt;
#pragma unroll
        for (int h = 0; h < 32; h++) {
            float2 wv = __ldg(&Wt2[h * 512 + t]);
            unsigned long long wxx = pack2(wv.x, wv.x);
            unsigned long long wyy = pack2(wv.y, wv.y);
            const float* row = o_sT + h * OPAD;
#pragma unroll
            for (int q4 = 0; q4 < 4; q4++) {
                ulonglong2 ov = *(const ulonglong2*)(row + q4 * 4);
                fma2(accA[q4 * 2 + 0], ov.x, wxx);
                fma2(accA[q4 * 2 + 1], ov.y, wxx);
                fma2(accB[q4 * 2 + 0], ov.x, wyy);
                fma2(accB[q4 * 2 + 1], ov.y, wyy);
            }
        }
#pragma unroll
        for (int p = 0; p < 8; p++) {
            float2 a = unpack2(accA[p]);
            float2 b = unpack2(accB[p]);
            *(float2*)(U_s + (p * 2 + 0) * 1024 + 2 * t) = make_float2(a.x, b.x);
            *(float2*)(U_s + (p * 2 + 1) * 1024 + 2 * t) = make_float2(a.y, b.y);
        }
    }
    __syncthreads();

    // edge phase: 4 edges per warp iter (16 warps)
    int estart = g_rowstart[n0];
    int eend = (n0 + NPB >= NN) ? EE : g_rowstart[n0 + NPB];
    float* aggdst = probe ? g_probe : g_agg;
    int osub = (lane & 7) * 4;
    for (int base = estart + w * 4; base < eend; base += 16 * 4) {
        int e = base + (lane >> 3);
        bool valid = e < eend;
        int sl = 0, d = 0;
        float4 q4 = make_float4(0.f, 0.f, 0.f, 0.f);
        if (valid) {
            sl = g_srcs[e] - n0;
            d = g_dsts[e];
            q4 = *(const float4*)(g_q + (size_t)e * 32 + osub);
        }
        const float* Ub = U_s + sl * 1024 + osub;
        float4 bt4 = *(const float4*)(bt_s + sl * 32 + osub);
        unsigned long long m01 = pack2(bt4.x, bt4.y);
        unsigned long long m23 = pack2(bt4.z, bt4.w);
#pragma unroll
        for (int k = 0; k < 32; k++) {
            float comp = (k & 3) == 0 ? q4.x : (k & 3) == 1 ? q4.y
                       : (k & 3) == 2 ? q4.z : q4.w;
            float qk = __shfl_sync(FULL, comp, (lane & 24) + (k >> 2));
            unsigned long long qq = pack2(qk, qk);
            ulonglong2 uv = *(const ulonglong2*)(Ub + k * 32);
            fma2(m01, uv.x, qq);
            fma2(m23, uv.y, qq);
        }
        if (valid) {
            float2 a = unpack2(m01), b = unpack2(m23);
            atomicAdd((float4*)(aggdst + (size_t)d * 32 + osub),
                      make_float4(a.x, a.y, b.x, b.y));
        }
    }
}

// R7 version: 256 threads, warp handles 4 nodes; re-zeroes agg
__global__ void __launch_bounds__(256) k_combine(
        const float* __restrict__ Wroot, const float* __restrict__ bconv,
        const float* __restrict__ bih, const float* __restrict__ bhh) {
    __shared__ float s_wr[1024];
    __shared__ float s_wi[3072];
    __shared__ float s_wh[3072];
    __shared__ float s_b[224];
    int t = threadIdx.x;
    for (int i = t; i < 1024; i += 256) s_wr[i] = Wroot[i];
    for (int i = t; i < 3072; i += 256) { s_wi[i] = g_WihT[i]; s_wh[i] = g_WhhT[i]; }
    if (t < 32) s_b[t] = bconv[t];
    if (t < 96) s_b[32 + t] = bih[t];
    if (t < 96) s_b[128 + t] = bhh[t];
    __syncthreads();

    int w = t >> 5, lane = t & 31;
    int n0 = (blockIdx.x * 8 + w) * 4;
    if (n0 >= NN) return;

    float hv[4], m[4];
#pragma unroll
    for (int r = 0; r < 4; r++) {
        int n = n0 + r;
        float aggv = g_agg[n * 32 + lane];
        g_agg[n * 32 + lane] = 0.f;
        hv[r] = g_out[n * 32 + lane];
        m[r] = s_b[lane] + aggv / fmaxf(g_deg[n], 1.f);
    }
#pragma unroll
    for (int h = 0; h < 32; h++) {
        float wr = s_wr[h * 32 + lane];
#pragma unroll
        for (int r = 0; r < 4; r++)
            m[r] = fmaf(__shfl_sync(FULL, hv[r], h), wr, m[r]);
    }
#pragma unroll
    for (int r = 0; r < 4; r++) m[r] = fmaxf(m[r], 0.f);

    float gr[4], gz[4], gn[4], hr[4], hz[4], hn[4];
#pragma unroll
    for (int r = 0; r < 4; r++) {
        gr[r] = s_b[32 + lane]; gz[r] = s_b[64 + lane]; gn[r] = s_b[96 + lane];
        hr[r] = s_b[128 + lane]; hz[r] = s_b[160 + lane]; hn[r] = s_b[192 + lane];
    }
#pragma unroll
    for (int h = 0; h < 32; h++) {
        float wi0 = s_wi[h * 96 + lane];
        float wi1 = s_wi[h * 96 + 32 + lane];
        float wi2 = s_wi[h * 96 + 64 + lane];
        float wh0 = s_wh[h * 96 + lane];
        float wh1 = s_wh[h * 96 + 32 + lane];
        float wh2 = s_wh[h * 96 + 64 + lane];
#pragma unroll
        for (int r = 0; r < 4; r++) {
            float mh = __shfl_sync(FULL, m[r], h);
            float hh = __shfl_sync(FULL, hv[r], h);
            gr[r] = fmaf(mh, wi0, gr[r]);
            gz[r] = fmaf(mh, wi1, gz[r]);
            gn[r] = fmaf(mh, wi2, gn[r]);
            hr[r] = fmaf(hh, wh0, hr[r]);
            hz[r] = fmaf(hh, wh1, hz[r]);
            hn[r] = fmaf(hh, wh2, hn[r]);
        }
    }
#pragma unroll
    for (int r = 0; r < 4; r++) {
        float rr = 1.f / (1.f + __expf(-(gr[r] + hr[r])));
        float zz = 1.f / (1.f + __expf(-(gz[r] + hz[r])));
        float nn2 = tanhf(gn[r] + rr * hn[r]);
        g_out[(n0 + r) * 32 + lane] = (1.f - zz) * nn2 + zz * hv[r];
    }
}

__global__ void k_pool(const int* __restrict__ batch) {
    int gt = blockIdx.x * blockDim.x + threadIdx.x;
    int n = gt >> 5, lane = gt & 31;
    if (n >= NN) return;
    int b = __ldg(&batch[n]);
    atomicAdd(&g_pooled[b * 32 + lane], g_out[n * 32 + lane]);
    if (lane == 0) { atomicAdd(&g_gcnt[b], 1.f); g_deg[n] = 0.f; }
}

__global__ void k_head(const float* __restrict__ W1a, const float* __restrict__ b1a,
                       const float* __restrict__ W1b, const float* __restrict__ b1b,
                       const float* __restrict__ W2a, const float* __restrict__ b2a,
                       const float* __restrict__ W2b, const float* __restrict__ b2b,
                       float* __restrict__ out, int out_size) {
    int gt = blockIdx.x * blockDim.x + threadIdx.x;
    int g = gt >> 5, lane = gt & 31;
    if (g >= GG) return;
    float c = fmaxf(g_gcnt[g], 1.f);
    float pm = g_pooled[g * 32 + lane] / c;
    g_pooled[g * 32 + lane] = 0.f;
    if (lane == 0) g_gcnt[g] = 0.f;
    float t1 = __ldg(&b1a[lane]);
    float t2 = __ldg(&b2a[lane]);
#pragma unroll
    for (int h = 0; h < 32; h++) {
        float ph = __shfl_sync(FULL, pm, h);
        t1 = fmaf(ph, __ldg(&W1a[h * 32 + lane]), t1);
        t2 = fmaf(ph, __ldg(&W2a[h * 32 + lane]), t2);
    }
    t1 = fmaxf(t1, 0.f);
    t2 = fmaxf(t2, 0.f);
    float lv = t1 * __ldg(&W1b[lane]);
    float d0 = t2 * __ldg(&W2b[lane * 2]);
    float d1 = t2 * __ldg(&W2b[lane * 2 + 1]);
#pragma unroll
    for (int off = 16; off; off >>= 1) {
        lv += __shfl_xor_sync(FULL, lv, off);
        d0 += __shfl_xor_sync(FULL, d0, off);
        d1 += __shfl_xor_sync(FULL, d1, off);
    }
    if (lane == 0) {
        float lab = lv + __ldg(&b1b[0]);
        float a0 = d0 + __ldg(&b2b[0]);
        float a1 = d1 + __ldg(&b2b[1]);
        float mx = fmaxf(a0, a1);
        float ls = mx + logf(expf(a0 - mx) + expf(a1 - mx));
        out[g] = lab;
        if (out_size >= GG * 3) {
            out[GG + g * 2]     = a0 - ls;
            out[GG + g * 2 + 1] = a1 - ls;
        }
    }
}

// ---------------- launch ----------------
extern "C" void kernel_launch(void* const* d_in, const int* in_sizes, int n_in,
                              void* d_out, int out_size) {
    const float* x     = (const float*)d_in[0];
    const float* ea    = (const float*)d_in[1];
    const int*   ei    = (const int*)d_in[2];
    const int*   batch = (const int*)d_in[3];
    const float* W0    = (const float*)d_in[5];
    const float* b0    = (const float*)d_in[6];
    const float* We1   = (const float*)d_in[7];
    const float* be1   = (const float*)d_in[8];
    const float* We2   = (const float*)d_in[9];
    const float* be2   = (const float*)d_in[10];
    const float* Wroot = (const float*)d_in[11];
    const float* bconv = (const float*)d_in[12];
    const float* Wih   = (const float*)d_in[13];
    const float* bih   = (const float*)d_in[14];
    const float* Whh   = (const float*)d_in[15];
    const float* bhh   = (const float*)d_in[16];
    const float* W1a   = (const float*)d_in[17];
    const float* b1a   = (const float*)d_in[18];
    const float* W1b   = (const float*)d_in[19];
    const float* b1b   = (const float*)d_in[20];
    const float* W2a   = (const float*)d_in[21];
    const float* b2a   = (const float*)d_in[22];
    const float* W2b   = (const float*)d_in[23];
    const float* b2b   = (const float*)d_in[24];
    float* out = (float*)d_out;

    const int TPB = 256;
    const int FUSE_SMEM = (16 * 1024 + 32 * OPAD + 16 * 32) * 4;  // 70144 B
    cudaFuncSetAttribute(k_fused, cudaFuncAttributeMaxDynamicSharedMemorySize, FUSE_SMEM);

    k_lin0<<<(NN + 7) / 8, 256>>>(x, W0, b0);                         // 1
    k_prep<<<(32 * 1024 + TPB - 1) / TPB, TPB>>>(We2, Wih, Whh);      // 2
    k_hist<<<(EE + TPB - 1) / TPB, TPB>>>(ei);                        // 3
    k_fused<<<296, FUSE_THREADS, FUSE_SMEM>>>(be2, 1);                // 4: ncu probe (2/SM)
    k_scan_block<<<NB_SCAN, 1024>>>();                                // 5
    k_scan_sums<<<1, 32>>>();                                         // 6
    k_scan_add<<<(NN + TPB - 1) / TPB, TPB>>>();                      // 7
    k_order<<<(EE + TPB - 1) / TPB, TPB>>>(ei);                       // 8
    k_permq<<<(EE + 7) / 8, 256>>>(ea, ei, We1, be1);                 // 9

    for (int it = 0; it < 3; it++) {
        k_fused<<<FUSE_GRID, FUSE_THREADS, FUSE_SMEM>>>(be2, 0);
        k_combine<<<(NN / 4 + 7) / 8, 256>>>(Wroot, bconv, bih, bhh);
    }

    k_pool<<<(NN * 32 + TPB - 1) / TPB, TPB>>>(batch);
    k_head<<<(GG * 32 + TPB - 1) / TPB, TPB>>>(W1a, b1a, W1b, b1b,
                                               W2a, b2a, W2b, b2b, out, out_size);
}

// round 13
// speedup vs baseline: 1.1886x; 1.0143x over previous
#include <cuda_runtime.h>
#include <math.h>

#define NN 50000
#define EE 250000
#define GG 512
#define NB_SCAN 49
#define NPB 16
#define FUSE_GRID (NN / NPB)            // 3125 exact
#define FUSE_THREADS 512
#define OPAD 20

// ---------------- device scratch (allocation-free) ----------------
__device__ float g_out[NN * 32];
__device__ float g_q[EE * 32];
__device__ float g_agg[NN * 32];        // invariant: zero at launch entry
__device__ float g_probe[NN * 32];      // probe-only sink
__device__ float g_Wt[32 * 1024];
__device__ float g_WihT[32 * 96];
__device__ float g_WhhT[32 * 96];
__device__ int   g_hist[NN];            // invariant: zero at entry
__device__ int   g_rowstart[NN + 32];
__device__ int   g_cursor[NN];
__device__ int   g_blocksum[NB_SCAN];
__device__ int   g_order[EE];
__device__ int   g_srcs[EE];
__device__ int   g_dsts[EE];
__device__ float g_deg[NN];             // invariant: zero at entry
__device__ float g_pooled[GG * 32];     // invariant: zero at entry
__device__ float g_gcnt[GG];            // invariant: zero at entry

#define FULL 0xffffffffu

__device__ __forceinline__ void fma2(unsigned long long& d,
                                     unsigned long long a, unsigned long long b) {
    asm("fma.rn.f32x2 %0, %1, %2, %0;" : "+l"(d) : "l"(a), "l"(b));
}
__device__ __forceinline__ unsigned long long pack2(float lo, float hi) {
    unsigned long long r;
    asm("mov.b64 %0, {%1, %2};" : "=l"(r) : "f"(lo), "f"(hi));
    return r;
}
__device__ __forceinline__ float2 unpack2(unsigned long long v) {
    float2 f;
    asm("mov.b64 {%0, %1}, %2;" : "=f"(f.x), "=f"(f.y) : "l"(v));
    return f;
}

// ---------------- kernels ----------------

__global__ void k_lin0(const float* __restrict__ x, const float* __restrict__ W0,
                       const float* __restrict__ b0) {
    __shared__ float s_w[1024];
    __shared__ float s_b[32];
    int t = threadIdx.x;
    for (int i = t; i < 1024; i += 256) s_w[i] = W0[i];
    if (t < 32) s_b[t] = b0[t];
    __syncthreads();
    int w = t >> 5, lane = t & 31;
    int n = blockIdx.x * 8 + w;
    if (n >= NN) return;
    float xv = x[n * 32 + lane];
    float acc = s_b[lane];
#pragma unroll
    for (int i = 0; i < 32; i++)
        acc = fmaf(__shfl_sync(FULL, xv, i), s_w[i * 32 + lane], acc);
    g_out[n * 32 + lane] = fmaxf(acc, 0.f);
}

__global__ void k_prep(const float* __restrict__ We2, const float* __restrict__ Wih,
                       const float* __restrict__ Whh) {
    int i = blockIdx.x * blockDim.x + threadIdx.x;
    if (i < 32 * 1024) {
        int h = i >> 10, c = i & 1023, k = c >> 5, o = c & 31;
        g_Wt[i] = We2[k * 1024 + h * 32 + o];
    }
    if (i < 32 * 96) {
        int h = i / 96, j = i % 96;
        g_WihT[i] = Wih[j * 32 + h];
        g_WhhT[i] = Whh[j * 32 + h];
    }
}

__global__ void k_hist(const int* __restrict__ ei) {
    int e = blockIdx.x * blockDim.x + threadIdx.x;
    if (e >= EE) return;
    atomicAdd(&g_hist[ei[e]], 1);
    atomicAdd(&g_deg[ei[EE + e]], 1.f);
}

__global__ void k_scan_block() {
    __shared__ int s[1024];
    int t = threadIdx.x;
    int i = blockIdx.x * 1024 + t;
    int v = (i < NN) ? g_hist[i] : 0;
    s[t] = v;
    __syncthreads();
#pragma unroll
    for (int off = 1; off < 1024; off <<= 1) {
        int xv = (t >= off) ? s[t - off] : 0;
        __syncthreads();
        s[t] += xv;
        __syncthreads();
    }
    if (i < NN) g_rowstart[i] = s[t] - v;
    if (t == 1023) g_blocksum[blockIdx.x] = s[1023];
}

// merged: computes its block offset from g_blocksum, applies, zeroes hist
__global__ void k_scan_add() {
    __shared__ int s_off;
    int t = threadIdx.x;
    if (t == 0) {
        int acc = 0;
        for (int b = 0; b < blockIdx.x; b++) acc += g_blocksum[b];
        s_off = acc;
    }
    __syncthreads();
    int i = blockIdx.x * 1024 + t;
    if (i >= NN) return;
    int v = g_rowstart[i] + s_off;
    g_rowstart[i] = v;
    g_cursor[i] = v;
    g_hist[i] = 0;
}

// writes order + sorted src/dst directly
__global__ void k_order(const int* __restrict__ ei) {
    int e = blockIdx.x * blockDim.x + threadIdx.x;
    if (e >= EE) return;
    int s = ei[e];
    int pos = atomicAdd(&g_cursor[s], 1);
    g_order[pos] = e;
    g_srcs[pos] = s;
    g_dsts[pos] = ei[EE + e];
}

__global__ void k_permq(const float* __restrict__ ea,
                        const float* __restrict__ We1, const float* __restrict__ be1) {
    __shared__ float s_w[512];
    __shared__ float s_b[32];
    int t = threadIdx.x;
    for (int i = t; i < 512; i += 256) s_w[i] = We1[i];
    if (t < 32) s_b[t] = be1[t];
    __syncthreads();
    int w = t >> 5, lane = t & 31;
    int i = blockIdx.x * 8 + w;
    if (i >= EE) return;
    int e = g_order[i];
    float eav = (lane < 16) ? __ldg(&ea[(size_t)e * 16 + lane]) : 0.f;
    float acc = s_b[lane];
#pragma unroll
    for (int k = 0; k < 16; k++)
        acc = fmaf(__shfl_sync(FULL, eav, k), s_w[k * 32 + lane], acc);
    g_q[(size_t)i * 32 + lane] = fmaxf(acc, 0.f);
}

// ---- FUSED (R12 champion): NPB=16, 2 blocks/SM, FFMA2 ----
__global__ void __launch_bounds__(FUSE_THREADS, 2) k_fused(const float* __restrict__ be2) {
    extern __shared__ float sm[];
    float* U_s  = sm;                               // [16][1024]
    float* o_sT = sm + 16 * 1024;                   // [32][OPAD]
    float* bt_s = sm + 16 * 1024 + 32 * OPAD;       // [16][32]

    int t = threadIdx.x, lane = t & 31, w = t >> 5;
    int n0 = blockIdx.x * NPB;

    {
        int n = t >> 5, h = t & 31;
        o_sT[h * OPAD + n] = g_out[n0 * 32 + t];
    }
    __syncthreads();

    {
        float acc = 0.f;
#pragma unroll
        for (int h = 0; h < 32; h++)
            acc = fmaf(o_sT[h * OPAD + w], __ldg(&be2[h * 32 + lane]), acc);
        bt_s[w * 32 + lane] = acc;
    }

    {
        unsigned long long accA[8], accB[8];
#pragma unroll
        for (int p = 0; p < 8; p++) { accA[p] = 0ull; accB[p] = 0ull; }
        const float2* Wt2 = (const float2*)g_Wt;
#pragma unroll
        for (int h = 0; h < 32; h++) {
            float2 wv = __ldg(&Wt2[h * 512 + t]);
            unsigned long long wxx = pack2(wv.x, wv.x);
            unsigned long long wyy = pack2(wv.y, wv.y);
            const float* row = o_sT + h * OPAD;
#pragma unroll
            for (int q4 = 0; q4 < 4; q4++) {
                ulonglong2 ov = *(const ulonglong2*)(row + q4 * 4);
                fma2(accA[q4 * 2 + 0], ov.x, wxx);
                fma2(accA[q4 * 2 + 1], ov.y, wxx);
                fma2(accB[q4 * 2 + 0], ov.x, wyy);
                fma2(accB[q4 * 2 + 1], ov.y, wyy);
            }
        }
#pragma unroll
        for (int p = 0; p < 8; p++) {
            float2 a = unpack2(accA[p]);
            float2 b = unpack2(accB[p]);
            *(float2*)(U_s + (p * 2 + 0) * 1024 + 2 * t) = make_float2(a.x, b.x);
            *(float2*)(U_s + (p * 2 + 1) * 1024 + 2 * t) = make_float2(a.y, b.y);
        }
    }
    __syncthreads();

    int estart = g_rowstart[n0];
    int eend = (n0 + NPB >= NN) ? EE : g_rowstart[n0 + NPB];
    int osub = (lane & 7) * 4;
    for (int base = estart + w * 4; base < eend; base += 16 * 4) {
        int e = base + (lane >> 3);
        bool valid = e < eend;
        int sl = 0, d = 0;
        float4 q4 = make_float4(0.f, 0.f, 0.f, 0.f);
        if (valid) {
            sl = g_srcs[e] - n0;
            d = g_dsts[e];
            q4 = *(const float4*)(g_q + (size_t)e * 32 + osub);
        }
        const float* Ub = U_s + sl * 1024 + osub;
        float4 bt4 = *(const float4*)(bt_s + sl * 32 + osub);
        unsigned long long m01 = pack2(bt4.x, bt4.y);
        unsigned long long m23 = pack2(bt4.z, bt4.w);
#pragma unroll
        for (int k = 0; k < 32; k++) {
            float comp = (k & 3) == 0 ? q4.x : (k & 3) == 1 ? q4.y
                       : (k & 3) == 2 ? q4.z : q4.w;
            float qk = __shfl_sync(FULL, comp, (lane & 24) + (k >> 2));
            unsigned long long qq = pack2(qk, qk);
            ulonglong2 uv = *(const ulonglong2*)(Ub + k * 32);
            fma2(m01, uv.x, qq);
            fma2(m23, uv.y, qq);
        }
        if (valid) {
            float2 a = unpack2(m01), b = unpack2(m23);
            atomicAdd((float4*)(g_agg + (size_t)d * 32 + osub),
                      make_float4(a.x, a.y, b.x, b.y));
        }
    }
}

// 256 threads, warp handles 4 nodes; probe mode writes g_probe, preserves state
__global__ void __launch_bounds__(256) k_combine(
        const float* __restrict__ Wroot, const float* __restrict__ bconv,
        const float* __restrict__ bih, const float* __restrict__ bhh, int probe) {
    __shared__ float s_wr[1024];
    __shared__ float s_wi[3072];
    __shared__ float s_wh[3072];
    __shared__ float s_b[224];
    int t = threadIdx.x;
    for (int i = t; i < 1024; i += 256) s_wr[i] = Wroot[i];
    for (int i = t; i < 3072; i += 256) { s_wi[i] = g_WihT[i]; s_wh[i] = g_WhhT[i]; }
    if (t < 32) s_b[t] = bconv[t];
    if (t < 96) s_b[32 + t] = bih[t];
    if (t < 96) s_b[128 + t] = bhh[t];
    __syncthreads();

    int w = t >> 5, lane = t & 31;
    int n0 = (blockIdx.x * 8 + w) * 4;
    if (n0 >= NN) return;

    float hv[4], m[4];
#pragma unroll
    for (int r = 0; r < 4; r++) {
        int n = n0 + r;
        float aggv = g_agg[n * 32 + lane];
        g_agg[n * 32 + lane] = 0.f;
        hv[r] = g_out[n * 32 + lane];
        m[r] = s_b[lane] + aggv / fmaxf(g_deg[n], 1.f);
    }
#pragma unroll
    for (int h = 0; h < 32; h++) {
        float wr = s_wr[h * 32 + lane];
#pragma unroll
        for (int r = 0; r < 4; r++)
            m[r] = fmaf(__shfl_sync(FULL, hv[r], h), wr, m[r]);
    }
#pragma unroll
    for (int r = 0; r < 4; r++) m[r] = fmaxf(m[r], 0.f);

    float gr[4], gz[4], gn[4], hr[4], hz[4], hn[4];
#pragma unroll
    for (int r = 0; r < 4; r++) {
        gr[r] = s_b[32 + lane]; gz[r] = s_b[64 + lane]; gn[r] = s_b[96 + lane];
        hr[r] = s_b[128 + lane]; hz[r] = s_b[160 + lane]; hn[r] = s_b[192 + lane];
    }
#pragma unroll
    for (int h = 0; h < 32; h++) {
        float wi0 = s_wi[h * 96 + lane];
        float wi1 = s_wi[h * 96 + 32 + lane];
        float wi2 = s_wi[h * 96 + 64 + lane];
        float wh0 = s_wh[h * 96 + lane];
        float wh1 = s_wh[h * 96 + 32 + lane];
        float wh2 = s_wh[h * 96 + 64 + lane];
#pragma unroll
        for (int r = 0; r < 4; r++) {
            float mh = __shfl_sync(FULL, m[r], h);
            float hh = __shfl_sync(FULL, hv[r], h);
            gr[r] = fmaf(mh, wi0, gr[r]);
            gz[r] = fmaf(mh, wi1, gz[r]);
            gn[r] = fmaf(mh, wi2, gn[r]);
            hr[r] = fmaf(hh, wh0, hr[r]);
            hz[r] = fmaf(hh, wh1, hz[r]);
            hn[r] = fmaf(hh, wh2, hn[r]);
        }
    }
    float* dst = probe ? g_probe : g_out;
#pragma unroll
    for (int r = 0; r < 4; r++) {
        float rr = 1.f / (1.f + __expf(-(gr[r] + hr[r])));
        float zz = 1.f / (1.f + __expf(-(gz[r] + hz[r])));
        float nn2 = tanhf(gn[r] + rr * hn[r]);
        dst[(n0 + r) * 32 + lane] = (1.f - zz) * nn2 + zz * hv[r];
    }
}

__global__ void k_pool(const int* __restrict__ batch) {
    int gt = blockIdx.x * blockDim.x + threadIdx.x;
    int n = gt >> 5, lane = gt & 31;
    if (n >= NN) return;
    int b = __ldg(&batch[n]);
    atomicAdd(&g_pooled[b * 32 + lane], g_out[n * 32 + lane]);
    if (lane == 0) { atomicAdd(&g_gcnt[b], 1.f); g_deg[n] = 0.f; }
}

__global__ void k_head(const float* __restrict__ W1a, const float* __restrict__ b1a,
                       const float* __restrict__ W1b, const float* __restrict__ b1b,
                       const float* __restrict__ W2a, const float* __restrict__ b2a,
                       const float* __restrict__ W2b, const float* __restrict__ b2b,
                       float* __restrict__ out, int out_size) {
    int gt = blockIdx.x * blockDim.x + threadIdx.x;
    int g = gt >> 5, lane = gt & 31;
    if (g >= GG) return;
    float c = fmaxf(g_gcnt[g], 1.f);
    float pm = g_pooled[g * 32 + lane] / c;
    g_pooled[g * 32 + lane] = 0.f;
    if (lane == 0) g_gcnt[g] = 0.f;
    float t1 = __ldg(&b1a[lane]);
    float t2 = __ldg(&b2a[lane]);
#pragma unroll
    for (int h = 0; h < 32; h++) {
        float ph = __shfl_sync(FULL, pm, h);
        t1 = fmaf(ph, __ldg(&W1a[h * 32 + lane]), t1);
        t2 = fmaf(ph, __ldg(&W2a[h * 32 + lane]), t2);
    }
    t1 = fmaxf(t1, 0.f);
    t2 = fmaxf(t2, 0.f);
    float lv = t1 * __ldg(&W1b[lane]);
    float d0 = t2 * __ldg(&W2b[lane * 2]);
    float d1 = t2 * __ldg(&W2b[lane * 2 + 1]);
#pragma unroll
    for (int off = 16; off; off >>= 1) {
        lv += __shfl_xor_sync(FULL, lv, off);
        d0 += __shfl_xor_sync(FULL, d0, off);
        d1 += __shfl_xor_sync(FULL, d1, off);
    }
    if (lane == 0) {
        float lab = lv + __ldg(&b1b[0]);
        float a0 = d0 + __ldg(&b2b[0]);
        float a1 = d1 + __ldg(&b2b[1]);
        float mx = fmaxf(a0, a1);
        float ls = mx + logf(expf(a0 - mx) + expf(a1 - mx));
        out[g] = lab;
        if (out_size >= GG * 3) {
            out[GG + g * 2]     = a0 - ls;
            out[GG + g * 2 + 1] = a1 - ls;
        }
    }
}

// ---------------- launch ----------------
extern "C" void kernel_launch(void* const* d_in, const int* in_sizes, int n_in,
                              void* d_out, int out_size) {
    const float* x     = (const float*)d_in[0];
    const float* ea    = (const float*)d_in[1];
    const int*   ei    = (const int*)d_in[2];
    const int*   batch = (const int*)d_in[3];
    const float* W0    = (const float*)d_in[5];
    const float* b0    = (const float*)d_in[6];
    const float* We1   = (const float*)d_in[7];
    const float* be1   = (const float*)d_in[8];
    const float* We2   = (const float*)d_in[9];
    const float* be2   = (const float*)d_in[10];
    const float* Wroot = (const float*)d_in[11];
    const float* bconv = (const float*)d_in[12];
    const float* Wih   = (const float*)d_in[13];
    const float* bih   = (const float*)d_in[14];
    const float* Whh   = (const float*)d_in[15];
    const float* bhh   = (const float*)d_in[16];
    const float* W1a   = (const float*)d_in[17];
    const float* b1a   = (const float*)d_in[18];
    const float* W1b   = (const float*)d_in[19];
    const float* b1b   = (const float*)d_in[20];
    const float* W2a   = (const float*)d_in[21];
    const float* b2a   = (const float*)d_in[22];
    const float* W2b   = (const float*)d_in[23];
    const float* b2b   = (const float*)d_in[24];
    float* out = (float*)d_out;

    const int TPB = 256;
    const int FUSE_SMEM = (16 * 1024 + 32 * OPAD + 16 * 32) * 4;  // 70144 B
    cudaFuncSetAttribute(k_fused, cudaFuncAttributeMaxDynamicSharedMemorySize, FUSE_SMEM);

    k_lin0<<<(NN + 7) / 8, 256>>>(x, W0, b0);                         // 1
    k_prep<<<(32 * 1024 + TPB - 1) / TPB, TPB>>>(We2, Wih, Whh);      // 2
    k_hist<<<(EE + TPB - 1) / TPB, TPB>>>(ei);                        // 3
    k_combine<<<148, 256>>>(Wroot, bconv, bih, bhh, 1);               // 4: ncu probe
    k_scan_block<<<NB_SCAN, 1024>>>();                                // 5
    k_scan_add<<<NB_SCAN, 1024>>>();                                  // 6
    k_order<<<(EE + TPB - 1) / TPB, TPB>>>(ei);                       // 7
    k_permq<<<(EE + 7) / 8, 256>>>(ea, We1, be1);                     // 8

    for (int it = 0; it < 3; it++) {
        k_fused<<<FUSE_GRID, FUSE_THREADS, FUSE_SMEM>>>(be2);
        k_combine<<<(NN / 4 + 7) / 8, 256>>>(Wroot, bconv, bih, bhh, 0);
    }

    k_pool<<<(NN * 32 + TPB - 1) / TPB, TPB>>>(batch);
    k_head<<<(GG * 32 + TPB - 1) / TPB, TPB>>>(W1a, b1a, W1b, b1b,
                                               W2a, b2a, W2b, b2b, out, out_size);
}

// round 14
// speedup vs baseline: 1.2028x; 1.0120x over previous
#include <cuda_runtime.h>
#include <math.h>

#define NN 50000
#define EE 250000
#define GG 512
#define NB_SCAN 49
#define NPB 16
#define FUSE_GRID (NN / NPB)            // 3125 exact
#define FUSE_THREADS 512
#define OPAD 20

// ---------------- device scratch (allocation-free) ----------------
__device__ float g_out[NN * 32];
__device__ float g_q[EE * 32];
__device__ float g_agg[NN * 32];        // invariant: zero at launch entry
__device__ float g_probe[NN * 32];      // probe-only sink
__device__ float g_Wt[32 * 1024];
__device__ float g_WihT[32 * 96];
__device__ float g_WhhT[32 * 96];
__device__ int   g_hist[NN];            // invariant: zero at entry
__device__ int   g_rowstart[NN + 32];
__device__ int   g_cursor[NN];
__device__ int   g_blocksum[NB_SCAN];
__device__ int   g_order[EE];
__device__ int   g_srcs[EE];
__device__ int   g_dsts[EE];
__device__ float g_deg[NN];             // invariant: zero at entry
__device__ float g_pooled[GG * 32];     // invariant: zero at entry
__device__ float g_gcnt[GG];            // invariant: zero at entry

#define FULL 0xffffffffu

__device__ __forceinline__ void fma2(unsigned long long& d,
                                     unsigned long long a, unsigned long long b) {
    asm("fma.rn.f32x2 %0, %1, %2, %0;" : "+l"(d) : "l"(a), "l"(b));
}
__device__ __forceinline__ unsigned long long pack2(float lo, float hi) {
    unsigned long long r;
    asm("mov.b64 %0, {%1, %2};" : "=l"(r) : "f"(lo), "f"(hi));
    return r;
}
__device__ __forceinline__ float2 unpack2(unsigned long long v) {
    float2 f;
    asm("mov.b64 {%0, %1}, %2;" : "=f"(f.x), "=f"(f.y) : "l"(v));
    return f;
}

// ---------------- kernels ----------------

__global__ void k_lin0(const float* __restrict__ x, const float* __restrict__ W0,
                       const float* __restrict__ b0) {
    __shared__ float s_w[1024];
    __shared__ float s_b[32];
    int t = threadIdx.x;
    for (int i = t; i < 1024; i += 256) s_w[i] = W0[i];
    if (t < 32) s_b[t] = b0[t];
    __syncthreads();
    int w = t >> 5, lane = t & 31;
    int n = blockIdx.x * 8 + w;
    if (n >= NN) return;
    float xv = x[n * 32 + lane];
    float acc = s_b[lane];
#pragma unroll
    for (int i = 0; i < 32; i++)
        acc = fmaf(__shfl_sync(FULL, xv, i), s_w[i * 32 + lane], acc);
    g_out[n * 32 + lane] = fmaxf(acc, 0.f);
}

__global__ void k_prep(const float* __restrict__ We2, const float* __restrict__ Wih,
                       const float* __restrict__ Whh) {
    int i = blockIdx.x * blockDim.x + threadIdx.x;
    if (i < 32 * 1024) {
        int h = i >> 10, c = i & 1023, k = c >> 5, o = c & 31;
        g_Wt[i] = We2[k * 1024 + h * 32 + o];
    }
    if (i < 32 * 96) {
        int h = i / 96, j = i % 96;
        g_WihT[i] = Wih[j * 32 + h];
        g_WhhT[i] = Whh[j * 32 + h];
    }
}

__global__ void k_hist(const int* __restrict__ ei) {
    int e = blockIdx.x * blockDim.x + threadIdx.x;
    if (e >= EE) return;
    atomicAdd(&g_hist[ei[e]], 1);
    atomicAdd(&g_deg[ei[EE + e]], 1.f);
}

__global__ void k_scan_block() {
    __shared__ int s[1024];
    int t = threadIdx.x;
    int i = blockIdx.x * 1024 + t;
    int v = (i < NN) ? g_hist[i] : 0;
    s[t] = v;
    __syncthreads();
#pragma unroll
    for (int off = 1; off < 1024; off <<= 1) {
        int xv = (t >= off) ? s[t - off] : 0;
        __syncthreads();
        s[t] += xv;
        __syncthreads();
    }
    if (i < NN) g_rowstart[i] = s[t] - v;
    if (t == 1023) g_blocksum[blockIdx.x] = s[1023];
}

__global__ void k_scan_add() {
    __shared__ int s_off;
    int t = threadIdx.x;
    if (t == 0) {
        int acc = 0;
        for (int b = 0; b < blockIdx.x; b++) acc += g_blocksum[b];
        s_off = acc;
    }
    __syncthreads();
    int i = blockIdx.x * 1024 + t;
    if (i >= NN) return;
    int v = g_rowstart[i] + s_off;
    g_rowstart[i] = v;
    g_cursor[i] = v;
    g_hist[i] = 0;
}

__global__ void k_order(const int* __restrict__ ei) {
    int e = blockIdx.x * blockDim.x + threadIdx.x;
    if (e >= EE) return;
    int s = ei[e];
    int pos = atomicAdd(&g_cursor[s], 1);
    g_order[pos] = e;
    g_srcs[pos] = s;
    g_dsts[pos] = ei[EE + e];
}

__global__ void k_permq(const float* __restrict__ ea,
                        const float* __restrict__ We1, const float* __restrict__ be1) {
    __shared__ float s_w[512];
    __shared__ float s_b[32];
    int t = threadIdx.x;
    for (int i = t; i < 512; i += 256) s_w[i] = We1[i];
    if (t < 32) s_b[t] = be1[t];
    __syncthreads();
    int w = t >> 5, lane = t & 31;
    int i = blockIdx.x * 8 + w;
    if (i >= EE) return;
    int e = g_order[i];
    float eav = (lane < 16) ? __ldg(&ea[(size_t)e * 16 + lane]) : 0.f;
    float acc = s_b[lane];
#pragma unroll
    for (int k = 0; k < 16; k++)
        acc = fmaf(__shfl_sync(FULL, eav, k), s_w[k * 32 + lane], acc);
    g_q[(size_t)i * 32 + lane] = fmaxf(acc, 0.f);
}

// ---- FUSED (R12 champion): NPB=16, 2 blocks/SM, FFMA2 ----
__global__ void __launch_bounds__(FUSE_THREADS, 2) k_fused(const float* __restrict__ be2) {
    extern __shared__ float sm[];
    float* U_s  = sm;                               // [16][1024]
    float* o_sT = sm + 16 * 1024;                   // [32][OPAD]
    float* bt_s = sm + 16 * 1024 + 32 * OPAD;       // [16][32]

    int t = threadIdx.x, lane = t & 31, w = t >> 5;
    int n0 = blockIdx.x * NPB;

    {
        int n = t >> 5, h = t & 31;
        o_sT[h * OPAD + n] = g_out[n0 * 32 + t];
    }
    __syncthreads();

    {
        float acc = 0.f;
#pragma unroll
        for (int h = 0; h < 32; h++)
            acc = fmaf(o_sT[h * OPAD + w], __ldg(&be2[h * 32 + lane]), acc);
        bt_s[w * 32 + lane] = acc;
    }

    {
        unsigned long long accA[8], accB[8];
#pragma unroll
        for (int p = 0; p < 8; p++) { accA[p] = 0ull; accB[p] = 0ull; }
        const float2* Wt2 = (const float2*)g_Wt;
#pragma unroll
        for (int h = 0; h < 32; h++) {
            float2 wv = __ldg(&Wt2[h * 512 + t]);
            unsigned long long wxx = pack2(wv.x, wv.x);
            unsigned long long wyy = pack2(wv.y, wv.y);
            const float* row = o_sT + h * OPAD;
#pragma unroll
            for (int q4 = 0; q4 < 4; q4++) {
                ulonglong2 ov = *(const ulonglong2*)(row + q4 * 4);
                fma2(accA[q4 * 2 + 0], ov.x, wxx);
                fma2(accA[q4 * 2 + 1], ov.y, wxx);
                fma2(accB[q4 * 2 + 0], ov.x, wyy);
                fma2(accB[q4 * 2 + 1], ov.y, wyy);
            }
        }
#pragma unroll
        for (int p = 0; p < 8; p++) {
            float2 a = unpack2(accA[p]);
            float2 b = unpack2(accB[p]);
            *(float2*)(U_s + (p * 2 + 0) * 1024 + 2 * t) = make_float2(a.x, b.x);
            *(float2*)(U_s + (p * 2 + 1) * 1024 + 2 * t) = make_float2(a.y, b.y);
        }
    }
    __syncthreads();

    int estart = g_rowstart[n0];
    int eend = (n0 + NPB >= NN) ? EE : g_rowstart[n0 + NPB];
    int osub = (lane & 7) * 4;
    for (int base = estart + w * 4; base < eend; base += 16 * 4) {
        int e = base + (lane >> 3);
        bool valid = e < eend;
        int sl = 0, d = 0;
        float4 q4 = make_float4(0.f, 0.f, 0.f, 0.f);
        if (valid) {
            sl = g_srcs[e] - n0;
            d = g_dsts[e];
            q4 = *(const float4*)(g_q + (size_t)e * 32 + osub);
        }
        const float* Ub = U_s + sl * 1024 + osub;
        float4 bt4 = *(const float4*)(bt_s + sl * 32 + osub);
        unsigned long long m01 = pack2(bt4.x, bt4.y);
        unsigned long long m23 = pack2(bt4.z, bt4.w);
#pragma unroll
        for (int k = 0; k < 32; k++) {
            float comp = (k & 3) == 0 ? q4.x : (k & 3) == 1 ? q4.y
                       : (k & 3) == 2 ? q4.z : q4.w;
            float qk = __shfl_sync(FULL, comp, (lane & 24) + (k >> 2));
            unsigned long long qq = pack2(qk, qk);
            ulonglong2 uv = *(const ulonglong2*)(Ub + k * 32);
            fma2(m01, uv.x, qq);
            fma2(m23, uv.y, qq);
        }
        if (valid) {
            float2 a = unpack2(m01), b = unpack2(m23);
            atomicAdd((float4*)(g_agg + (size_t)d * 32 + osub),
                      make_float4(a.x, a.y, b.x, b.y));
        }
    }
}

// 256 threads, warp handles 4 nodes; limited unroll + 3 blocks/SM target
__global__ void __launch_bounds__(256, 3) k_combine(
        const float* __restrict__ Wroot, const float* __restrict__ bconv,
        const float* __restrict__ bih, const float* __restrict__ bhh, int probe) {
    __shared__ float s_wr[1024];
    __shared__ float s_wi[3072];
    __shared__ float s_wh[3072];
    __shared__ float s_b[224];
    int t = threadIdx.x;
    for (int i = t; i < 1024; i += 256) s_wr[i] = Wroot[i];
    for (int i = t; i < 3072; i += 256) { s_wi[i] = g_WihT[i]; s_wh[i] = g_WhhT[i]; }
    if (t < 32) s_b[t] = bconv[t];
    if (t < 96) s_b[32 + t] = bih[t];
    if (t < 96) s_b[128 + t] = bhh[t];
    __syncthreads();

    int w = t >> 5, lane = t & 31;
    int n0 = (blockIdx.x * 8 + w) * 4;
    if (n0 >= NN) return;

    float hv[4], m[4];
#pragma unroll
    for (int r = 0; r < 4; r++) {
        int n = n0 + r;
        float aggv = g_agg[n * 32 + lane];
        g_agg[n * 32 + lane] = 0.f;
        hv[r] = g_out[n * 32 + lane];
        m[r] = s_b[lane] + aggv / fmaxf(g_deg[n], 1.f);
    }
#pragma unroll 4
    for (int h = 0; h < 32; h++) {
        float wr = s_wr[h * 32 + lane];
#pragma unroll
        for (int r = 0; r < 4; r++)
            m[r] = fmaf(__shfl_sync(FULL, hv[r], h), wr, m[r]);
    }
#pragma unroll
    for (int r = 0; r < 4; r++) m[r] = fmaxf(m[r], 0.f);

    float gr[4], gz[4], gn[4], hr[4], hz[4], hn[4];
#pragma unroll
    for (int r = 0; r < 4; r++) {
        gr[r] = s_b[32 + lane]; gz[r] = s_b[64 + lane]; gn[r] = s_b[96 + lane];
        hr[r] = s_b[128 + lane]; hz[r] = s_b[160 + lane]; hn[r] = s_b[192 + lane];
    }
#pragma unroll 4
    for (int h = 0; h < 32; h++) {
        float wi0 = s_wi[h * 96 + lane];
        float wi1 = s_wi[h * 96 + 32 + lane];
        float wi2 = s_wi[h * 96 + 64 + lane];
        float wh0 = s_wh[h * 96 + lane];
        float wh1 = s_wh[h * 96 + 32 + lane];
        float wh2 = s_wh[h * 96 + 64 + lane];
#pragma unroll
        for (int r = 0; r < 4; r++) {
            float mh = __shfl_sync(FULL, m[r], h);
            float hh = __shfl_sync(FULL, hv[r], h);
            gr[r] = fmaf(mh, wi0, gr[r]);
            gz[r] = fmaf(mh, wi1, gz[r]);
            gn[r] = fmaf(mh, wi2, gn[r]);
            hr[r] = fmaf(hh, wh0, hr[r]);
            hz[r] = fmaf(hh, wh1, hz[r]);
            hn[r] = fmaf(hh, wh2, hn[r]);
        }
    }
    float* dst = probe ? g_probe : g_out;
#pragma unroll
    for (int r = 0; r < 4; r++) {
        float rr = 1.f / (1.f + __expf(-(gr[r] + hr[r])));
        float zz = 1.f / (1.f + __expf(-(gz[r] + hz[r])));
        float nn2 = tanhf(gn[r] + rr * hn[r]);
        dst[(n0 + r) * 32 + lane] = (1.f - zz) * nn2 + zz * hv[r];
    }
}

__global__ void k_pool(const int* __restrict__ batch) {
    int gt = blockIdx.x * blockDim.x + threadIdx.x;
    int n = gt >> 5, lane = gt & 31;
    if (n >= NN) return;
    int b = __ldg(&batch[n]);
    atomicAdd(&g_pooled[b * 32 + lane], g_out[n * 32 + lane]);
    if (lane == 0) { atomicAdd(&g_gcnt[b], 1.f); g_deg[n] = 0.f; }
}

__global__ void k_head(const float* __restrict__ W1a, const float* __restrict__ b1a,
                       const float* __restrict__ W1b, const float* __restrict__ b1b,
                       const float* __restrict__ W2a, const float* __restrict__ b2a,
                       const float* __restrict__ W2b, const float* __restrict__ b2b,
                       float* __restrict__ out, int out_size) {
    int gt = blockIdx.x * blockDim.x + threadIdx.x;
    int g = gt >> 5, lane = gt & 31;
    if (g >= GG) return;
    float c = fmaxf(g_gcnt[g], 1.f);
    float pm = g_pooled[g * 32 + lane] / c;
    g_pooled[g * 32 + lane] = 0.f;
    if (lane == 0) g_gcnt[g] = 0.f;
    float t1 = __ldg(&b1a[lane]);
    float t2 = __ldg(&b2a[lane]);
#pragma unroll
    for (int h = 0; h < 32; h++) {
        float ph = __shfl_sync(FULL, pm, h);
        t1 = fmaf(ph, __ldg(&W1a[h * 32 + lane]), t1);
        t2 = fmaf(ph, __ldg(&W2a[h * 32 + lane]), t2);
    }
    t1 = fmaxf(t1, 0.f);
    t2 = fmaxf(t2, 0.f);
    float lv = t1 * __ldg(&W1b[lane]);
    float d0 = t2 * __ldg(&W2b[lane * 2]);
    float d1 = t2 * __ldg(&W2b[lane * 2 + 1]);
#pragma unroll
    for (int off = 16; off; off >>= 1) {
        lv += __shfl_xor_sync(FULL, lv, off);
        d0 += __shfl_xor_sync(FULL, d0, off);
        d1 += __shfl_xor_sync(FULL, d1, off);
    }
    if (lane == 0) {
        float lab = lv + __ldg(&b1b[0]);
        float a0 = d0 + __ldg(&b2b[0]);
        float a1 = d1 + __ldg(&b2b[1]);
        float mx = fmaxf(a0, a1);
        float ls = mx + logf(expf(a0 - mx) + expf(a1 - mx));
        out[g] = lab;
        if (out_size >= GG * 3) {
            out[GG + g * 2]     = a0 - ls;
            out[GG + g * 2 + 1] = a1 - ls;
        }
    }
}

// ---------------- launch ----------------
extern "C" void kernel_launch(void* const* d_in, const int* in_sizes, int n_in,
                              void* d_out, int out_size) {
    const float* x     = (const float*)d_in[0];
    const float* ea    = (const float*)d_in[1];
    const int*   ei    = (const int*)d_in[2];
    const int*   batch = (const int*)d_in[3];
    const float* W0    = (const float*)d_in[5];
    const float* b0    = (const float*)d_in[6];
    const float* We1   = (const float*)d_in[7];
    const float* be1   = (const float*)d_in[8];
    const float* We2   = (const float*)d_in[9];
    const float* be2   = (const float*)d_in[10];
    const float* Wroot = (const float*)d_in[11];
    const float* bconv = (const float*)d_in[12];
    const float* Wih   = (const float*)d_in[13];
    const float* bih   = (const float*)d_in[14];
    const float* Whh   = (const float*)d_in[15];
    const float* bhh   = (const float*)d_in[16];
    const float* W1a   = (const float*)d_in[17];
    const float* b1a   = (const float*)d_in[18];
    const float* W1b   = (const float*)d_in[19];
    const float* b1b   = (const float*)d_in[20];
    const float* W2a   = (const float*)d_in[21];
    const float* b2a   = (const float*)d_in[22];
    const float* W2b   = (const float*)d_in[23];
    const float* b2b   = (const float*)d_in[24];
    float* out = (float*)d_out;

    const int TPB = 256;
    const int FUSE_SMEM = (16 * 1024 + 32 * OPAD + 16 * 32) * 4;  // 70144 B
    cudaFuncSetAttribute(k_fused, cudaFuncAttributeMaxDynamicSharedMemorySize, FUSE_SMEM);

    k_lin0<<<(NN + 7) / 8, 256>>>(x, W0, b0);                         // 1
    k_prep<<<(32 * 1024 + TPB - 1) / TPB, TPB>>>(We2, Wih, Whh);      // 2
    k_hist<<<(EE + TPB - 1) / TPB, TPB>>>(ei);                        // 3
    k_combine<<<148, 256>>>(Wroot, bconv, bih, bhh, 1);               // 4: ncu probe
    k_scan_block<<<NB_SCAN, 1024>>>();                                // 5
    k_scan_add<<<NB_SCAN, 1024>>>();                                  // 6
    k_order<<<(EE + TPB - 1) / TPB, TPB>>>(ei);                       // 7
    k_permq<<<(EE + 7) / 8, 256>>>(ea, We1, be1);                     // 8

    for (int it = 0; it < 3; it++) {
        k_fused<<<FUSE_GRID, FUSE_THREADS, FUSE_SMEM>>>(be2);
        k_combine<<<(NN / 4 + 7) / 8, 256>>>(Wroot, bconv, bih, bhh, 0);
    }

    k_pool<<<(NN * 32 + TPB - 1) / TPB, TPB>>>(batch);
    k_head<<<(GG * 32 + TPB - 1) / TPB, TPB>>>(W1a, b1a, W1b, b1b,
                                               W2a, b2a, W2b, b2b, out, out_size);
}

// round 15
// speedup vs baseline: 1.3006x; 1.0813x over previous
#include <cuda_runtime.h>
#include <math.h>

#define NN 50000
#define EE 250000
#define GG 512
#define NB_SCAN 49
#define NPB 16
#define FUSE_GRID (NN / NPB)            // 3125 exact
#define FUSE_THREADS 512
#define OPAD 20

// ---------------- device scratch (allocation-free) ----------------
__device__ float g_out[NN * 32];
__device__ float g_q[EE * 32];
__device__ float g_agg[NN * 32];        // invariant: zero at launch entry
__device__ float g_Wt[32 * 1024];
__device__ float g_WihT[32 * 96];
__device__ float g_WhhT[32 * 96];
__device__ int   g_hist[NN];            // invariant: zero at entry
__device__ int   g_rowstart[NN + 32];
__device__ int   g_cursor[NN];
__device__ int   g_blocksum[NB_SCAN];
__device__ int   g_order[EE];
__device__ int   g_srcs[EE];
__device__ int   g_dsts[EE];
__device__ float g_deg[NN];             // invariant: zero at entry
__device__ float g_pooled[GG * 32];     // invariant: zero at entry
__device__ float g_gcnt[GG];            // invariant: zero at entry

#define FULL 0xffffffffu

__device__ __forceinline__ void fma2(unsigned long long& d,
                                     unsigned long long a, unsigned long long b) {
    asm("fma.rn.f32x2 %0, %1, %2, %0;" : "+l"(d) : "l"(a), "l"(b));
}
__device__ __forceinline__ unsigned long long pack2(float lo, float hi) {
    unsigned long long r;
    asm("mov.b64 %0, {%1, %2};" : "=l"(r) : "f"(lo), "f"(hi));
    return r;
}
__device__ __forceinline__ float2 unpack2(unsigned long long v) {
    float2 f;
    asm("mov.b64 {%0, %1}, %2;" : "=f"(f.x), "=f"(f.y) : "l"(v));
    return f;
}

// ---------------- kernels ----------------

// 256 threads, 2 nodes per warp -> 16 nodes/block
__global__ void k_lin0(const float* __restrict__ x, const float* __restrict__ W0,
                       const float* __restrict__ b0) {
    __shared__ float s_w[1024];
    __shared__ float s_b[32];
    int t = threadIdx.x;
    for (int i = t; i < 1024; i += 256) s_w[i] = W0[i];
    if (t < 32) s_b[t] = b0[t];
    __syncthreads();
    int w = t >> 5, lane = t & 31;
#pragma unroll
    for (int r = 0; r < 2; r++) {
        int n = blockIdx.x * 16 + w + r * 8;
        if (n >= NN) continue;
        float xv = x[n * 32 + lane];
        float acc = s_b[lane];
#pragma unroll
        for (int i = 0; i < 32; i++)
            acc = fmaf(__shfl_sync(FULL, xv, i), s_w[i * 32 + lane], acc);
        g_out[n * 32 + lane] = fmaxf(acc, 0.f);
    }
}

__global__ void k_prep(const float* __restrict__ We2, const float* __restrict__ Wih,
                       const float* __restrict__ Whh) {
    int i = blockIdx.x * blockDim.x + threadIdx.x;
    if (i < 32 * 1024) {
        int h = i >> 10, c = i & 1023, k = c >> 5, o = c & 31;
        g_Wt[i] = We2[k * 1024 + h * 32 + o];
    }
    if (i < 32 * 96) {
        int h = i / 96, j = i % 96;
        g_WihT[i] = Wih[j * 32 + h];
        g_WhhT[i] = Whh[j * 32 + h];
    }
}

__global__ void k_hist(const int* __restrict__ ei) {
    int e = blockIdx.x * blockDim.x + threadIdx.x;
    if (e >= EE) return;
    atomicAdd(&g_hist[ei[e]], 1);
    atomicAdd(&g_deg[ei[EE + e]], 1.f);
}

__global__ void k_scan_block() {
    __shared__ int s[1024];
    int t = threadIdx.x;
    int i = blockIdx.x * 1024 + t;
    int v = (i < NN) ? g_hist[i] : 0;
    s[t] = v;
    __syncthreads();
#pragma unroll
    for (int off = 1; off < 1024; off <<= 1) {
        int xv = (t >= off) ? s[t - off] : 0;
        __syncthreads();
        s[t] += xv;
        __syncthreads();
    }
    if (i < NN) g_rowstart[i] = s[t] - v;
    if (t == 1023) g_blocksum[blockIdx.x] = s[1023];
}

__global__ void k_scan_add() {
    __shared__ int s_off;
    int t = threadIdx.x;
    if (t == 0) {
        int acc = 0;
        for (int b = 0; b < blockIdx.x; b++) acc += g_blocksum[b];
        s_off = acc;
    }
    __syncthreads();
    int i = blockIdx.x * 1024 + t;
    if (i >= NN) return;
    int v = g_rowstart[i] + s_off;
    g_rowstart[i] = v;
    g_cursor[i] = v;
    g_hist[i] = 0;
}

__global__ void k_order(const int* __restrict__ ei) {
    int e = blockIdx.x * blockDim.x + threadIdx.x;
    if (e >= EE) return;
    int s = ei[e];
    int pos = atomicAdd(&g_cursor[s], 1);
    g_order[pos] = e;
    g_srcs[pos] = s;
    g_dsts[pos] = ei[EE + e];
}

// 256 threads, 2 edges per warp -> 16 edges/block
__global__ void k_permq(const float* __restrict__ ea,
                        const float* __restrict__ We1, const float* __restrict__ be1) {
    __shared__ float s_w[512];
    __shared__ float s_b[32];
    int t = threadIdx.x;
    for (int i = t; i < 512; i += 256) s_w[i] = We1[i];
    if (t < 32) s_b[t] = be1[t];
    __syncthreads();
    int w = t >> 5, lane = t & 31;
#pragma unroll
    for (int r = 0; r < 2; r++) {
        int i = blockIdx.x * 16 + w + r * 8;
        if (i >= EE) continue;
        int e = g_order[i];
        float eav = (lane < 16) ? __ldg(&ea[(size_t)e * 16 + lane]) : 0.f;
        float acc = s_b[lane];
#pragma unroll
        for (int k = 0; k < 16; k++)
            acc = fmaf(__shfl_sync(FULL, eav, k), s_w[k * 32 + lane], acc);
        g_q[(size_t)i * 32 + lane] = fmaxf(acc, 0.f);
    }
}

// ---- FUSED (R12 champion): NPB=16, 2 blocks/SM, FFMA2 ----
__global__ void __launch_bounds__(FUSE_THREADS, 2) k_fused(const float* __restrict__ be2) {
    extern __shared__ float sm[];
    float* U_s  = sm;                               // [16][1024]
    float* o_sT = sm + 16 * 1024;                   // [32][OPAD]
    float* bt_s = sm + 16 * 1024 + 32 * OPAD;       // [16][32]

    int t = threadIdx.x, lane = t & 31, w = t >> 5;
    int n0 = blockIdx.x * NPB;

    {
        int n = t >> 5, h = t & 31;
        o_sT[h * OPAD + n] = g_out[n0 * 32 + t];
    }
    __syncthreads();

    {
        float acc = 0.f;
#pragma unroll
        for (int h = 0; h < 32; h++)
            acc = fmaf(o_sT[h * OPAD + w], __ldg(&be2[h * 32 + lane]), acc);
        bt_s[w * 32 + lane] = acc;
    }

    {
        unsigned long long accA[8], accB[8];
#pragma unroll
        for (int p = 0; p < 8; p++) { accA[p] = 0ull; accB[p] = 0ull; }
        const float2* Wt2 = (const float2*)g_Wt;
#pragma unroll
        for (int h = 0; h < 32; h++) {
            float2 wv = __ldg(&Wt2[h * 512 + t]);
            unsigned long long wxx = pack2(wv.x, wv.x);
            unsigned long long wyy = pack2(wv.y, wv.y);
            const float* row = o_sT + h * OPAD;
#pragma unroll
            for (int q4 = 0; q4 < 4; q4++) {
                ulonglong2 ov = *(const ulonglong2*)(row + q4 * 4);
                fma2(accA[q4 * 2 + 0], ov.x, wxx);
                fma2(accA[q4 * 2 + 1], ov.y, wxx);
                fma2(accB[q4 * 2 + 0], ov.x, wyy);
                fma2(accB[q4 * 2 + 1], ov.y, wyy);
            }
        }
#pragma unroll
        for (int p = 0; p < 8; p++) {
            float2 a = unpack2(accA[p]);
            float2 b = unpack2(accB[p]);
            *(float2*)(U_s + (p * 2 + 0) * 1024 + 2 * t) = make_float2(a.x, b.x);
            *(float2*)(U_s + (p * 2 + 1) * 1024 + 2 * t) = make_float2(a.y, b.y);
        }
    }
    __syncthreads();

    int estart = g_rowstart[n0];
    int eend = (n0 + NPB >= NN) ? EE : g_rowstart[n0 + NPB];
    int osub = (lane & 7) * 4;
    for (int base = estart + w * 4; base < eend; base += 16 * 4) {
        int e = base + (lane >> 3);
        bool valid = e < eend;
        int sl = 0, d = 0;
        float4 q4 = make_float4(0.f, 0.f, 0.f, 0.f);
        if (valid) {
            sl = g_srcs[e] - n0;
            d = g_dsts[e];
            q4 = *(const float4*)(g_q + (size_t)e * 32 + osub);
        }
        const float* Ub = U_s + sl * 1024 + osub;
        float4 bt4 = *(const float4*)(bt_s + sl * 32 + osub);
        unsigned long long m01 = pack2(bt4.x, bt4.y);
        unsigned long long m23 = pack2(bt4.z, bt4.w);
#pragma unroll
        for (int k = 0; k < 32; k++) {
            float comp = (k & 3) == 0 ? q4.x : (k & 3) == 1 ? q4.y
                       : (k & 3) == 2 ? q4.z : q4.w;
            float qk = __shfl_sync(FULL, comp, (lane & 24) + (k >> 2));
            unsigned long long qq = pack2(qk, qk);
            ulonglong2 uv = *(const ulonglong2*)(Ub + k * 32);
            fma2(m01, uv.x, qq);
            fma2(m23, uv.y, qq);
        }
        if (valid) {
            float2 a = unpack2(m01), b = unpack2(m23);
            atomicAdd((float4*)(g_agg + (size_t)d * 32 + osub),
                      make_float4(a.x, a.y, b.x, b.y));
        }
    }
}

// 256 threads, warp handles 4 nodes; limited unroll, 3 blocks/SM
__global__ void __launch_bounds__(256, 3) k_combine(
        const float* __restrict__ Wroot, const float* __restrict__ bconv,
        const float* __restrict__ bih, const float* __restrict__ bhh) {
    __shared__ float s_wr[1024];
    __shared__ float s_wi[3072];
    __shared__ float s_wh[3072];
    __shared__ float s_b[224];
    int t = threadIdx.x;
    for (int i = t; i < 1024; i += 256) s_wr[i] = Wroot[i];
    for (int i = t; i < 3072; i += 256) { s_wi[i] = g_WihT[i]; s_wh[i] = g_WhhT[i]; }
    if (t < 32) s_b[t] = bconv[t];
    if (t < 96) s_b[32 + t] = bih[t];
    if (t < 96) s_b[128 + t] = bhh[t];
    __syncthreads();

    int w = t >> 5, lane = t & 31;
    int n0 = (blockIdx.x * 8 + w) * 4;
    if (n0 >= NN) return;

    float hv[4], m[4];
#pragma unroll
    for (int r = 0; r < 4; r++) {
        int n = n0 + r;
        float aggv = g_agg[n * 32 + lane];
        g_agg[n * 32 + lane] = 0.f;
        hv[r] = g_out[n * 32 + lane];
        m[r] = s_b[lane] + aggv / fmaxf(g_deg[n], 1.f);
    }
#pragma unroll 4
    for (int h = 0; h < 32; h++) {
        float wr = s_wr[h * 32 + lane];
#pragma unroll
        for (int r = 0; r < 4; r++)
            m[r] = fmaf(__shfl_sync(FULL, hv[r], h), wr, m[r]);
    }
#pragma unroll
    for (int r = 0; r < 4; r++) m[r] = fmaxf(m[r], 0.f);

    float gr[4], gz[4], gn[4], hr[4], hz[4], hn[4];
#pragma unroll
    for (int r = 0; r < 4; r++) {
        gr[r] = s_b[32 + lane]; gz[r] = s_b[64 + lane]; gn[r] = s_b[96 + lane];
        hr[r] = s_b[128 + lane]; hz[r] = s_b[160 + lane]; hn[r] = s_b[192 + lane];
    }
#pragma unroll 4
    for (int h = 0; h < 32; h++) {
        float wi0 = s_wi[h * 96 + lane];
        float wi1 = s_wi[h * 96 + 32 + lane];
        float wi2 = s_wi[h * 96 + 64 + lane];
        float wh0 = s_wh[h * 96 + lane];
        float wh1 = s_wh[h * 96 + 32 + lane];
        float wh2 = s_wh[h * 96 + 64 + lane];
#pragma unroll
        for (int r = 0; r < 4; r++) {
            float mh = __shfl_sync(FULL, m[r], h);
            float hh = __shfl_sync(FULL, hv[r], h);
            gr[r] = fmaf(mh, wi0, gr[r]);
            gz[r] = fmaf(mh, wi1, gz[r]);
            gn[r] = fmaf(mh, wi2, gn[r]);
            hr[r] = fmaf(hh, wh0, hr[r]);
            hz[r] = fmaf(hh, wh1, hz[r]);
            hn[r] = fmaf(hh, wh2, hn[r]);
        }
    }
#pragma unroll
    for (int r = 0; r < 4; r++) {
        float rr = 1.f / (1.f + __expf(-(gr[r] + hr[r])));
        float zz = 1.f / (1.f + __expf(-(gz[r] + hz[r])));
        float nn2 = tanhf(gn[r] + rr * hn[r]);
        g_out[(n0 + r) * 32 + lane] = (1.f - zz) * nn2 + zz * hv[r];
    }
}

__global__ void k_pool(const int* __restrict__ batch) {
    int gt = blockIdx.x * blockDim.x + threadIdx.x;
    int n = gt >> 5, lane = gt & 31;
    if (n >= NN) return;
    int b = __ldg(&batch[n]);
    atomicAdd(&g_pooled[b * 32 + lane], g_out[n * 32 + lane]);
    if (lane == 0) { atomicAdd(&g_gcnt[b], 1.f); g_deg[n] = 0.f; }
}

__global__ void k_head(const float* __restrict__ W1a, const float* __restrict__ b1a,
                       const float* __restrict__ W1b, const float* __restrict__ b1b,
                       const float* __restrict__ W2a, const float* __restrict__ b2a,
                       const float* __restrict__ W2b, const float* __restrict__ b2b,
                       float* __restrict__ out, int out_size) {
    int gt = blockIdx.x * blockDim.x + threadIdx.x;
    int g = gt >> 5, lane = gt & 31;
    if (g >= GG) return;
    float c = fmaxf(g_gcnt[g], 1.f);
    float pm = g_pooled[g * 32 + lane] / c;
    g_pooled[g * 32 + lane] = 0.f;
    if (lane == 0) g_gcnt[g] = 0.f;
    float t1 = __ldg(&b1a[lane]);
    float t2 = __ldg(&b2a[lane]);
#pragma unroll
    for (int h = 0; h < 32; h++) {
        float ph = __shfl_sync(FULL, pm, h);
        t1 = fmaf(ph, __ldg(&W1a[h * 32 + lane]), t1);
        t2 = fmaf(ph, __ldg(&W2a[h * 32 + lane]), t2);
    }
    t1 = fmaxf(t1, 0.f);
    t2 = fmaxf(t2, 0.f);
    float lv = t1 * __ldg(&W1b[lane]);
    float d0 = t2 * __ldg(&W2b[lane * 2]);
    float d1 = t2 * __ldg(&W2b[lane * 2 + 1]);
#pragma unroll
    for (int off = 16; off; off >>= 1) {
        lv += __shfl_xor_sync(FULL, lv, off);
        d0 += __shfl_xor_sync(FULL, d0, off);
        d1 += __shfl_xor_sync(FULL, d1, off);
    }
    if (lane == 0) {
        float lab = lv + __ldg(&b1b[0]);
        float a0 = d0 + __ldg(&b2b[0]);
        float a1 = d1 + __ldg(&b2b[1]);
        float mx = fmaxf(a0, a1);
        float ls = mx + logf(expf(a0 - mx) + expf(a1 - mx));
        out[g] = lab;
        if (out_size >= GG * 3) {
            out[GG + g * 2]     = a0 - ls;
            out[GG + g * 2 + 1] = a1 - ls;
        }
    }
}

// ---------------- launch ----------------
extern "C" void kernel_launch(void* const* d_in, const int* in_sizes, int n_in,
                              void* d_out, int out_size) {
    const float* x     = (const float*)d_in[0];
    const float* ea    = (const float*)d_in[1];
    const int*   ei    = (const int*)d_in[2];
    const int*   batch = (const int*)d_in[3];
    const float* W0    = (const float*)d_in[5];
    const float* b0    = (const float*)d_in[6];
    const float* We1   = (const float*)d_in[7];
    const float* be1   = (const float*)d_in[8];
    const float* We2   = (const float*)d_in[9];
    const float* be2   = (const float*)d_in[10];
    const float* Wroot = (const float*)d_in[11];
    const float* bconv = (const float*)d_in[12];
    const float* Wih   = (const float*)d_in[13];
    const float* bih   = (const float*)d_in[14];
    const float* Whh   = (const float*)d_in[15];
    const float* bhh   = (const float*)d_in[16];
    const float* W1a   = (const float*)d_in[17];
    const float* b1a   = (const float*)d_in[18];
    const float* W1b   = (const float*)d_in[19];
    const float* b1b   = (const float*)d_in[20];
    const float* W2a   = (const float*)d_in[21];
    const float* b2a   = (const float*)d_in[22];
    const float* W2b   = (const float*)d_in[23];
    const float* b2b   = (const float*)d_in[24];
    float* out = (float*)d_out;

    const int TPB = 256;
    const int FUSE_SMEM = (16 * 1024 + 32 * OPAD + 16 * 32) * 4;  // 70144 B
    cudaFuncSetAttribute(k_fused, cudaFuncAttributeMaxDynamicSharedMemorySize, FUSE_SMEM);

    k_lin0<<<(NN + 15) / 16, 256>>>(x, W0, b0);
    k_prep<<<(32 * 1024 + TPB - 1) / TPB, TPB>>>(We2, Wih, Whh);
    k_hist<<<(EE + TPB - 1) / TPB, TPB>>>(ei);
    k_scan_block<<<NB_SCAN, 1024>>>();
    k_scan_add<<<NB_SCAN, 1024>>>();
    k_order<<<(EE + TPB - 1) / TPB, TPB>>>(ei);
    k_permq<<<(EE + 15) / 16, 256>>>(ea, We1, be1);

    for (int it = 0; it < 3; it++) {
        k_fused<<<FUSE_GRID, FUSE_THREADS, FUSE_SMEM>>>(be2);
        k_combine<<<(NN / 4 + 7) / 8, 256>>>(Wroot, bconv, bih, bhh);
    }

    k_pool<<<(NN * 32 + TPB - 1) / TPB, TPB>>>(batch);
    k_head<<<(GG * 32 + TPB - 1) / TPB, TPB>>>(W1a, b1a, W1b, b1b,
                                               W2a, b2a, W2b, b2b, out, out_size);
}